// round 7
// baseline (speedup 1.0000x reference)
#include <cuda_runtime.h>
#include <cuda_bf16.h>
#include <math.h>
#include <stdint.h>

#define NN 100000
#define NE 500000
#define DIMC 256
#define NH 8

// Dynamic smem layout (bytes):
//   A stage s (s=0,1): base + s*20480   -> Ah at +0, Al at +10240
//   B stage s:         base + 40960 + s*20480 -> Bh at +0, Bl at +10240
#define STAGE_BYTES 20480
#define HALF_BYTES  10240
#define B_BASE      40960
#define DYN_SMEM    81920

// ---------------------------------------------------------------------------
// Device-global scratch (no allocation allowed in kernel_launch)
// ---------------------------------------------------------------------------
__device__ float g_Q[NN * DIMC];
__device__ float g_K[NN * DIMC];
__device__ float g_V[NN * DIMC];
__device__ float g_wV[NN * DIMC];
__device__ float g_Z[NN * NH];
__device__ float g_S[NE * NH];
__device__ float g_cs[DIMC];
__device__ float g_cs2[DIMC];
__device__ int g_src[NE];
__device__ int g_dst[NE];
__device__ __nv_bfloat16 g_Wh[768 * DIMC], g_Wl[768 * DIMC];     // [n][k], QKV concat
__device__ __nv_bfloat16 g_WEh[DIMC * DIMC], g_WEl[DIMC * DIMC]; // [n][k]

// ---------------------------------------------------------------------------
// Warp-MMA helpers (portable PTX: ldmatrix + mma.sync + cp.async, sm_80+)
// ---------------------------------------------------------------------------
__device__ __forceinline__ uint32_t smem_u32(const void* p) {
    uint32_t a;
    asm("{ .reg .u64 t; cvta.to.shared.u64 t, %1; cvt.u32.u64 %0, t; }"
        : "=r"(a) : "l"(p));
    return a;
}
__device__ __forceinline__ void ldsm_x4(uint32_t* r, uint32_t addr) {
    asm volatile("ldmatrix.sync.aligned.m8n8.x4.shared.b16 {%0,%1,%2,%3}, [%4];"
                 : "=r"(r[0]), "=r"(r[1]), "=r"(r[2]), "=r"(r[3]) : "r"(addr));
}
__device__ __forceinline__ void ldsm_x2(uint32_t* r, uint32_t addr) {
    asm volatile("ldmatrix.sync.aligned.m8n8.x2.shared.b16 {%0,%1}, [%2];"
                 : "=r"(r[0]), "=r"(r[1]) : "r"(addr));
}
__device__ __forceinline__ void mma_bf16(float* d, const uint32_t* a, const uint32_t* b) {
    asm volatile(
        "mma.sync.aligned.m16n8k16.row.col.f32.bf16.bf16.f32 "
        "{%0,%1,%2,%3}, {%4,%5,%6,%7}, {%8,%9}, {%0,%1,%2,%3};"
        : "+f"(d[0]), "+f"(d[1]), "+f"(d[2]), "+f"(d[3])
        : "r"(a[0]), "r"(a[1]), "r"(a[2]), "r"(a[3]), "r"(b[0]), "r"(b[1]));
}
__device__ __forceinline__ void cp_async16(uint32_t saddr, const void* gptr) {
    asm volatile("cp.async.cg.shared.global [%0], [%1], 16;"
                 :: "r"(saddr), "l"(gptr) : "memory");
}
__device__ __forceinline__ void cp_commit() {
    asm volatile("cp.async.commit_group;" ::: "memory");
}
__device__ __forceinline__ void cp_wait0() {
    asm volatile("cp.async.wait_group 0;" ::: "memory");
}

// ---------------------------------------------------------------------------
// Zero atomically-updated accumulators.
// ---------------------------------------------------------------------------
__global__ void zero_kernel() {
    long total = (long)NN * DIMC + (long)NN * NH;
    long stride = (long)gridDim.x * blockDim.x;
    for (long i = (long)blockIdx.x * blockDim.x + threadIdx.x; i < total; i += stride) {
        if (i < (long)NN * DIMC) g_wV[i] = 0.0f;
        else                     g_Z[i - (long)NN * DIMC] = 0.0f;
    }
    if (blockIdx.x == 0 && threadIdx.x < DIMC) {
        g_cs[threadIdx.x]  = 0.0f;
        g_cs2[threadIdx.x] = 0.0f;
    }
}

// ---------------------------------------------------------------------------
// edge_index -> int32 src/dst (handles int64 or int32 payload, deterministic)
// ---------------------------------------------------------------------------
__global__ void cvt_idx_kernel(const long long* __restrict__ e64) {
    const int* e32 = (const int*)e64;
    bool is64 = true;
    #pragma unroll
    for (int i = 0; i < 64; ++i)
        if ((e64[i] >> 32) != 0) is64 = false;
    long stride = (long)gridDim.x * blockDim.x;
    for (long e = (long)blockIdx.x * blockDim.x + threadIdx.x; e < NE; e += stride) {
        if (is64) { g_src[e] = (int)e64[e]; g_dst[e] = (int)e64[NE + e]; }
        else      { g_src[e] = e32[e];      g_dst[e] = e32[NE + e];      }
    }
}

// ---------------------------------------------------------------------------
// Weights transposed into B-operand layout [n][k], split hi/lo. (Tiny.)
// ---------------------------------------------------------------------------
__global__ void prep_w_kernel(const float* __restrict__ WQ, const float* __restrict__ WK,
                              const float* __restrict__ WV, const float* __restrict__ WE) {
    int i = blockIdx.x * 256 + threadIdx.x;   // 0 .. 1024*256-1
    if (i < 768 * DIMC) {
        int n = i >> 8;
        int k = i & 255;
        int m = n >> 8, nn = n & 255;
        const float* W = (m == 0) ? WQ : (m == 1) ? WK : WV;
        float v = W[k * DIMC + nn];
        __nv_bfloat16 h = __float2bfloat16(v);
        g_Wh[i] = h;
        g_Wl[i] = __float2bfloat16(v - __bfloat162float(h));
    } else {
        int j = i - 768 * DIMC;
        int n = j >> 8, k = j & 255;
        float v = WE[k * DIMC + n];
        __nv_bfloat16 h = __float2bfloat16(v);
        g_WEh[j] = h;
        g_WEl[j] = __float2bfloat16(v - __bfloat162float(h));
    }
}

// ---------------------------------------------------------------------------
// Convert & store one A chunk (4 float4 per thread) to hi/lo bf16 smem stage.
// ---------------------------------------------------------------------------
__device__ __forceinline__ void stsA(char* stage, const float4* v4,
                                     const int* aRow, int aC4) {
    __nv_bfloat16* sAh = (__nv_bfloat16*)stage;
    __nv_bfloat16* sAl = (__nv_bfloat16*)(stage + HALF_BYTES);
    #pragma unroll
    for (int l = 0; l < 4; ++l) {
        float4 v = v4[l];
        __nv_bfloat162 h01 = __floats2bfloat162_rn(v.x, v.y);
        __nv_bfloat162 h23 = __floats2bfloat162_rn(v.z, v.w);
        __nv_bfloat162 l01 = __floats2bfloat162_rn(v.x - __low2float(h01),
                                                   v.y - __high2float(h01));
        __nv_bfloat162 l23 = __floats2bfloat162_rn(v.z - __low2float(h23),
                                                   v.w - __high2float(h23));
        int row = aRow[l];
        *(uint2*)(sAh + row * 40 + aC4 * 4) =
            make_uint2(*(uint32_t*)&h01, *(uint32_t*)&h23);
        *(uint2*)(sAl + row * 40 + aC4 * 4) =
            make_uint2(*(uint32_t*)&l01, *(uint32_t*)&l23);
    }
}

// ---------------------------------------------------------------------------
// Warp-MMA split-bf16 GEMM, 128x128 block tile, K=256 in 8 chunks of 32.
// MMA-first pipeline (per iter):
//   issue cp.async B(kc+1) -> other stage ; MMA(kc) ; STS A(kc+1) -> other
//   stage ; LDG A(kc+2) ; wait B(kc+1) ; bar
// so B-load latency and A conversion hide behind the MMA section.
// 8 warps in 4(M) x 2(N); each warp computes 32x64 via m16n8k16 bf16 mma.
// 3 MMAs per (mi,ni,k16): Ah*Bh + Ah*Bl + Al*Bh  (fp32 accumulate).
// EDGE=0: writes Q/K/V.  EDGE=1: per-edge head-score epilogue -> g_S.
// ---------------------------------------------------------------------------
template<int EDGE>
__global__ void __launch_bounds__(256, 2) mma_gemm_kernel(const float* __restrict__ Asrc) {
    extern __shared__ __align__(16) char dsm[];
    __shared__ int Ssrc[128], Sdst[128];

    const int tid  = threadIdx.x;
    const int wid  = tid >> 5;
    const int lane = tid & 31;
    const int wm   = wid & 3;
    const int wn   = wid >> 2;
    const int quad = lane & 3;
    const int qrow = lane >> 2;

    const int row0  = blockIdx.x * 128;
    const int nbase = blockIdx.y * 128;
    const int Mtot  = EDGE ? NE : NN;

    if (EDGE && tid < 128) {
        int ge = row0 + tid;
        if (ge > NE - 1) ge = NE - 1;
        Ssrc[tid] = g_src[ge];
        Sdst[tid] = g_dst[ge];
    }

    const float4* A4 = (const float4*)Asrc;
    const uint4* Bh4 = EDGE ? (const uint4*)g_WEh : (const uint4*)g_Wh;
    const uint4* Bl4 = EDGE ? (const uint4*)g_WEl : (const uint4*)g_Wl;

    float acc[2][8][4] = {};

    const uint32_t base = smem_u32(dsm);
    const uint32_t aOff = (uint32_t)((wm * 32 + (lane & 15)) * 80 + (lane >> 4) * 16);
    const uint32_t bOffRow = (uint32_t)((wn * 64 + (lane & 7)) * 80 + ((lane >> 3) & 1) * 16);

    // Per-thread fixed staging coords.
    const int aRow[4] = { (tid + 0) >> 3, (tid + 256) >> 3, (tid + 512) >> 3, (tid + 768) >> 3 };
    const int aC4 = tid & 7;
    long aRowG[4];
    #pragma unroll
    for (int l = 0; l < 4; ++l) aRowG[l] = min(row0 + aRow[l], Mtot - 1);
    // B staging: idx = tid + l*256; sel = idx>>9; w = idx&511; row=w>>2; c4=w&3.
    const int bSel[4] = { (tid + 0) >> 9 ? 1 : 0, (tid + 256) >> 9 ? 1 : 0,
                          (tid + 512) >> 9 ? 1 : 0, (tid + 768) >> 9 ? 1 : 0 };
    int bRow[4], bC4[4];
    #pragma unroll
    for (int l = 0; l < 4; ++l) {
        int w = (tid + l * 256) & 511;
        bRow[l] = w >> 2;
        bC4[l]  = w & 3;
    }

    // ---- prologue ----
    float4 aPre[4];
    #pragma unroll
    for (int l = 0; l < 4; ++l) aPre[l] = A4[aRowG[l] * 64 + 0 + aC4];
    {
        uint32_t bB = base + B_BASE;   // stage 0
        #pragma unroll
        for (int l = 0; l < 4; ++l) {
            const uint4* gsrc = (bSel[l] ? Bl4 : Bh4) + (long)(nbase + bRow[l]) * 32 + 0 + bC4[l];
            cp_async16(bB + (uint32_t)(bSel[l] * HALF_BYTES + bRow[l] * 80 + bC4[l] * 16), gsrc);
        }
        cp_commit();
    }
    stsA(dsm, aPre, aRow, aC4);   // A(0) -> stage 0
    #pragma unroll
    for (int l = 0; l < 4; ++l) aPre[l] = A4[aRowG[l] * 64 + 8 + aC4];  // A(1)
    cp_wait0();
    __syncthreads();

    for (int kc = 0; kc < 8; ++kc) {
        const int st = kc & 1;
        const uint32_t aBase = base + st * STAGE_BYTES;
        const uint32_t bBase = base + B_BASE + st * STAGE_BYTES;

        // Issue B(kc+1) into the other stage (its readers finished last bar).
        if (kc < 7) {
            uint32_t bBn = base + B_BASE + (st ^ 1) * STAGE_BYTES;
            #pragma unroll
            for (int l = 0; l < 4; ++l) {
                const uint4* gsrc = (bSel[l] ? Bl4 : Bh4) +
                                    (long)(nbase + bRow[l]) * 32 + (kc + 1) * 4 + bC4[l];
                cp_async16(bBn + (uint32_t)(bSel[l] * HALF_BYTES + bRow[l] * 80 + bC4[l] * 16), gsrc);
            }
            cp_commit();
        }

        // ---- MMA on stage st ----
        #pragma unroll
        for (int s = 0; s < 2; ++s) {
            uint32_t ah[2][4], al[2][4];
            #pragma unroll
            for (int mi = 0; mi < 2; ++mi) {
                uint32_t o = aOff + (uint32_t)(mi * 16 * 80 + s * 32);
                ldsm_x4(ah[mi], aBase + o);
                ldsm_x4(al[mi], aBase + HALF_BYTES + o);
            }
            #pragma unroll
            for (int ni = 0; ni < 8; ++ni) {
                uint32_t bo = bOffRow + (uint32_t)(ni * 8 * 80 + s * 32);
                uint32_t bh[2], bl[2];
                ldsm_x2(bh, bBase + bo);
                ldsm_x2(bl, bBase + HALF_BYTES + bo);
                #pragma unroll
                for (int mi = 0; mi < 2; ++mi) {
                    mma_bf16(acc[mi][ni], ah[mi], bh);
                    mma_bf16(acc[mi][ni], ah[mi], bl);
                    mma_bf16(acc[mi][ni], al[mi], bh);
                }
            }
        }

        // ---- stage (kc+1): STS A, prefetch A(kc+2), wait B(kc+1) ----
        if (kc < 7) {
            stsA(dsm + (st ^ 1) * STAGE_BYTES, aPre, aRow, aC4);
            if (kc < 6) {
                #pragma unroll
                for (int l = 0; l < 4; ++l)
                    aPre[l] = A4[aRowG[l] * 64 + (kc + 2) * 8 + aC4];
            }
            cp_wait0();
            __syncthreads();
        }
    }

    if (EDGE) {
        // Per-edge head scores for this tile's 4 heads -> g_S.
        const float scale = 0.17677669529663687f;  // 1/sqrt(32)
        #pragma unroll
        for (int mi = 0; mi < 2; ++mi) {
            #pragma unroll
            for (int rh = 0; rh < 2; ++rh) {
                int r  = wm * 32 + mi * 16 + qrow + rh * 8;
                int ge = row0 + r;
                const float* Kr = g_K + (long)Ssrc[r] * DIMC + nbase + wn * 64;
                const float* Qr = g_Q + (long)Sdst[r] * DIMC + nbase + wn * 64;
                #pragma unroll
                for (int h = 0; h < 2; ++h) {
                    float p = 0.0f;
                    #pragma unroll
                    for (int j = 0; j < 4; ++j) {
                        int ni = h * 4 + j;
                        int c  = ni * 8 + quad * 2;
                        float2 kv = *(const float2*)(Kr + c);
                        float2 qv = *(const float2*)(Qr + c);
                        p += acc[mi][ni][rh * 2 + 0] * kv.x * qv.x;
                        p += acc[mi][ni][rh * 2 + 1] * kv.y * qv.y;
                    }
                    p += __shfl_xor_sync(0xffffffffu, p, 1);
                    p += __shfl_xor_sync(0xffffffffu, p, 2);
                    if (quad == 0 && ge < NE) {
                        float sv = fminf(5.0f, fmaxf(-5.0f, p * scale));
                        g_S[(long)ge * NH + (nbase >> 5) + wn * 2 + h] = expf(sv);
                    }
                }
            }
        }
    } else {
        int by = blockIdx.y;
        float* Cout = (by < 2) ? g_Q : (by < 4) ? g_K : g_V;
        int colb = (by & 1) * 128;
        #pragma unroll
        for (int mi = 0; mi < 2; ++mi) {
            #pragma unroll
            for (int ni = 0; ni < 8; ++ni) {
                int r = row0 + wm * 32 + mi * 16 + qrow;
                int c = colb + wn * 64 + ni * 8 + quad * 2;
                if (r < NN)
                    *(float2*)(Cout + (long)r * DIMC + c) =
                        make_float2(acc[mi][ni][0], acc[mi][ni][1]);
                if (r + 8 < NN)
                    *(float2*)(Cout + (long)(r + 8) * DIMC + c) =
                        make_float2(acc[mi][ni][2], acc[mi][ni][3]);
            }
        }
    }
}

// ---------------------------------------------------------------------------
// Scatter: wV[dst] += V[src]*score ; Z[dst,h] += score.  64 edges per block.
// Thread t: column group (t&63)*4 (float4), edge quarter (t>>6)*16.
// ---------------------------------------------------------------------------
__global__ void scatter_kernel() {
    __shared__ int ssrc[64], sdst[64];
    __shared__ float ssc[64][NH];
    int e0 = blockIdx.x * 64;
    int tid = threadIdx.x;
    if (tid < 64) {
        int ge = e0 + tid;
        ssrc[tid] = (ge < NE) ? g_src[ge] : 0;
        sdst[tid] = (ge < NE) ? g_dst[ge] : 0;
    }
    for (int p = tid; p < 64 * NH; p += 256) {
        int el = p >> 3, h = p & 7;
        int ge = e0 + el;
        ssc[el][h] = (ge < NE) ? g_S[(long)ge * NH + h] : 0.0f;
    }
    __syncthreads();
    int cg = (tid & 63) * 4;
    int h  = cg >> 5;
    int ebeg = (tid >> 6) * 16;
    #pragma unroll 4
    for (int el = ebeg; el < ebeg + 16; ++el) {
        int ge = e0 + el;
        if (ge < NE) {
            float s = ssc[el][h];
            float4 v = *(const float4*)(g_V + (long)ssrc[el] * DIMC + cg);
            float* w = g_wV + (long)sdst[el] * DIMC + cg;
            atomicAdd(w + 0, v.x * s);
            atomicAdd(w + 1, v.y * s);
            atomicAdd(w + 2, v.z * s);
            atomicAdd(w + 3, v.w * s);
        }
    }
    for (int p = tid; p < 64 * NH; p += 256) {
        int el = p >> 3, h2 = p & 7;
        int ge = e0 + el;
        if (ge < NE) atomicAdd(&g_Z[(long)sdst[el] * NH + h2], ssc[el][h2]);
    }
}

// ---------------------------------------------------------------------------
// Residual + BN column stats, then normalize.
// ---------------------------------------------------------------------------
__global__ void resid_stats_kernel(const float* __restrict__ x, float* __restrict__ out) {
    int c = threadIdx.x;
    int r0 = blockIdx.x * 256;
    int rend = min(NN, r0 + 256);
    float s = 0.0f, s2 = 0.0f;
    for (int n = r0; n < rend; ++n) {
        float z = g_Z[(long)n * NH + (c >> 5)] + 1e-6f;
        float h = x[(long)n * DIMC + c] + g_wV[(long)n * DIMC + c] / z;
        out[(long)n * DIMC + c] = h;
        s += h;
        s2 += h * h;
    }
    atomicAdd(&g_cs[c], s);
    atomicAdd(&g_cs2[c], s2);
}

__global__ void bn_norm_kernel(float* __restrict__ out,
                               const float* __restrict__ gamma,
                               const float* __restrict__ beta) {
    long total = (long)NN * DIMC;
    long stride = (long)gridDim.x * blockDim.x;
    const float invN = 1.0f / (float)NN;
    for (long i = (long)blockIdx.x * blockDim.x + threadIdx.x; i < total; i += stride) {
        int c = (int)(i & (DIMC - 1));
        float mean = g_cs[c] * invN;
        float var = g_cs2[c] * invN - mean * mean;
        out[i] = (out[i] - mean) * rsqrtf(var + 1e-5f) * gamma[c] + beta[c];
    }
}

extern "C" void kernel_launch(void* const* d_in, const int* in_sizes, int n_in,
                              void* d_out, int out_size) {
    const float* x     = (const float*)d_in[0];
    const float* ea    = (const float*)d_in[1];
    const float* WQ    = (const float*)d_in[2];
    const float* WK    = (const float*)d_in[3];
    const float* WE    = (const float*)d_in[4];
    const float* WV    = (const float*)d_in[5];
    const float* gamma = (const float*)d_in[6];
    const float* beta  = (const float*)d_in[7];
    const long long* eidx = (const long long*)d_in[8];
    float* out = (float*)d_out;

    // Opt-in to >48KB dynamic smem (attribute set, not an allocation).
    cudaFuncSetAttribute(mma_gemm_kernel<0>,
                         cudaFuncAttributeMaxDynamicSharedMemorySize, DYN_SMEM);
    cudaFuncSetAttribute(mma_gemm_kernel<1>,
                         cudaFuncAttributeMaxDynamicSharedMemorySize, DYN_SMEM);

    zero_kernel<<<1024, 256>>>();
    cvt_idx_kernel<<<512, 256>>>(eidx);
    prep_w_kernel<<<1024, 256>>>(WQ, WK, WV, WE);

    // QKV: C[100000,768] -> 782 x 6 tiles of 128x128 (A = x, converted in-kernel)
    mma_gemm_kernel<0><<<dim3(782, 6), 256, DYN_SMEM>>>(x);
    // Edge: Eh GEMM + fused score epilogue -> 3907 x 2 tiles
    mma_gemm_kernel<1><<<dim3(3907, 2), 256, DYN_SMEM>>>(ea);

    scatter_kernel<<<(NE + 63) / 64, 256>>>();
    resid_stats_kernel<<<(NN + 255) / 256, 256>>>(x, out);
    bn_norm_kernel<<<2048, 256>>>(out, gamma, beta);
}

// round 8
// speedup vs baseline: 1.1357x; 1.1357x over previous
#include <cuda_runtime.h>
#include <cuda_bf16.h>
#include <math.h>
#include <stdint.h>

#define NN 100000
#define NE 500000
#define DIMC 256
#define NH 8

// Dynamic smem layout (bytes):
//   A stage s (s=0,1): base + s*20480   -> Ah at +0, Al at +10240
//   B stage s:         base + 40960 + s*20480 -> Bh at +0, Bl at +10240
#define STAGE_BYTES 20480
#define HALF_BYTES  10240
#define B_BASE      40960
#define DYN_SMEM    81920

// ---------------------------------------------------------------------------
// Device-global scratch (no allocation allowed in kernel_launch)
// ---------------------------------------------------------------------------
__device__ float g_Q[NN * DIMC];
__device__ float g_K[NN * DIMC];
__device__ float g_V[NN * DIMC];
__device__ float g_wV[NN * DIMC];
__device__ float g_Z[NN * NH];
__device__ float g_S[NE * NH];
__device__ float g_cs[DIMC];
__device__ float g_cs2[DIMC];
__device__ int g_src[NE];
__device__ int g_dst[NE];
__device__ __nv_bfloat16 g_Wh[768 * DIMC], g_Wl[768 * DIMC];     // [n][k], QKV concat
__device__ __nv_bfloat16 g_WEh[DIMC * DIMC], g_WEl[DIMC * DIMC]; // [n][k]

// ---------------------------------------------------------------------------
// Warp-MMA helpers (portable PTX: ldmatrix + mma.sync + cp.async, sm_80+)
// ---------------------------------------------------------------------------
__device__ __forceinline__ uint32_t smem_u32(const void* p) {
    uint32_t a;
    asm("{ .reg .u64 t; cvta.to.shared.u64 t, %1; cvt.u32.u64 %0, t; }"
        : "=r"(a) : "l"(p));
    return a;
}
__device__ __forceinline__ void ldsm_x4(uint32_t* r, uint32_t addr) {
    asm volatile("ldmatrix.sync.aligned.m8n8.x4.shared.b16 {%0,%1,%2,%3}, [%4];"
                 : "=r"(r[0]), "=r"(r[1]), "=r"(r[2]), "=r"(r[3]) : "r"(addr));
}
__device__ __forceinline__ void ldsm_x2(uint32_t* r, uint32_t addr) {
    asm volatile("ldmatrix.sync.aligned.m8n8.x2.shared.b16 {%0,%1}, [%2];"
                 : "=r"(r[0]), "=r"(r[1]) : "r"(addr));
}
__device__ __forceinline__ void mma_bf16(float* d, const uint32_t* a, const uint32_t* b) {
    asm volatile(
        "mma.sync.aligned.m16n8k16.row.col.f32.bf16.bf16.f32 "
        "{%0,%1,%2,%3}, {%4,%5,%6,%7}, {%8,%9}, {%0,%1,%2,%3};"
        : "+f"(d[0]), "+f"(d[1]), "+f"(d[2]), "+f"(d[3])
        : "r"(a[0]), "r"(a[1]), "r"(a[2]), "r"(a[3]), "r"(b[0]), "r"(b[1]));
}
__device__ __forceinline__ void cp_async16(uint32_t saddr, const void* gptr) {
    asm volatile("cp.async.cg.shared.global [%0], [%1], 16;"
                 :: "r"(saddr), "l"(gptr) : "memory");
}
__device__ __forceinline__ void cp_commit() {
    asm volatile("cp.async.commit_group;" ::: "memory");
}
__device__ __forceinline__ void cp_wait0() {
    asm volatile("cp.async.wait_group 0;" ::: "memory");
}

// ---------------------------------------------------------------------------
// Zero atomically-updated accumulators.
// ---------------------------------------------------------------------------
__global__ void zero_kernel() {
    long total = (long)NN * DIMC + (long)NN * NH;
    long stride = (long)gridDim.x * blockDim.x;
    for (long i = (long)blockIdx.x * blockDim.x + threadIdx.x; i < total; i += stride) {
        if (i < (long)NN * DIMC) g_wV[i] = 0.0f;
        else                     g_Z[i - (long)NN * DIMC] = 0.0f;
    }
    if (blockIdx.x == 0 && threadIdx.x < DIMC) {
        g_cs[threadIdx.x]  = 0.0f;
        g_cs2[threadIdx.x] = 0.0f;
    }
}

// ---------------------------------------------------------------------------
// edge_index -> int32 src/dst (handles int64 or int32 payload, deterministic)
// ---------------------------------------------------------------------------
__global__ void cvt_idx_kernel(const long long* __restrict__ e64) {
    const int* e32 = (const int*)e64;
    bool is64 = true;
    #pragma unroll
    for (int i = 0; i < 64; ++i)
        if ((e64[i] >> 32) != 0) is64 = false;
    long stride = (long)gridDim.x * blockDim.x;
    for (long e = (long)blockIdx.x * blockDim.x + threadIdx.x; e < NE; e += stride) {
        if (is64) { g_src[e] = (int)e64[e]; g_dst[e] = (int)e64[NE + e]; }
        else      { g_src[e] = e32[e];      g_dst[e] = e32[NE + e];      }
    }
}

// ---------------------------------------------------------------------------
// Weights transposed into B-operand layout [n][k], split hi/lo. (Tiny.)
// ---------------------------------------------------------------------------
__global__ void prep_w_kernel(const float* __restrict__ WQ, const float* __restrict__ WK,
                              const float* __restrict__ WV, const float* __restrict__ WE) {
    int i = blockIdx.x * 256 + threadIdx.x;   // 0 .. 1024*256-1
    if (i < 768 * DIMC) {
        int n = i >> 8;
        int k = i & 255;
        int m = n >> 8, nn = n & 255;
        const float* W = (m == 0) ? WQ : (m == 1) ? WK : WV;
        float v = W[k * DIMC + nn];
        __nv_bfloat16 h = __float2bfloat16(v);
        g_Wh[i] = h;
        g_Wl[i] = __float2bfloat16(v - __bfloat162float(h));
    } else {
        int j = i - 768 * DIMC;
        int n = j >> 8, k = j & 255;
        float v = WE[k * DIMC + n];
        __nv_bfloat16 h = __float2bfloat16(v);
        g_WEh[j] = h;
        g_WEl[j] = __float2bfloat16(v - __bfloat162float(h));
    }
}

// ---------------------------------------------------------------------------
// Convert & store one A chunk (4 float4 per thread) to hi/lo bf16 smem stage.
// ---------------------------------------------------------------------------
__device__ __forceinline__ void stsA(char* stage, const float4* v4,
                                     const int* aRow, int aC4) {
    __nv_bfloat16* sAh = (__nv_bfloat16*)stage;
    __nv_bfloat16* sAl = (__nv_bfloat16*)(stage + HALF_BYTES);
    #pragma unroll
    for (int l = 0; l < 4; ++l) {
        float4 v = v4[l];
        __nv_bfloat162 h01 = __floats2bfloat162_rn(v.x, v.y);
        __nv_bfloat162 h23 = __floats2bfloat162_rn(v.z, v.w);
        __nv_bfloat162 l01 = __floats2bfloat162_rn(v.x - __low2float(h01),
                                                   v.y - __high2float(h01));
        __nv_bfloat162 l23 = __floats2bfloat162_rn(v.z - __low2float(h23),
                                                   v.w - __high2float(h23));
        int row = aRow[l];
        *(uint2*)(sAh + row * 40 + aC4 * 4) =
            make_uint2(*(uint32_t*)&h01, *(uint32_t*)&h23);
        *(uint2*)(sAl + row * 40 + aC4 * 4) =
            make_uint2(*(uint32_t*)&l01, *(uint32_t*)&l23);
    }
}

// ---------------------------------------------------------------------------
// Warp-MMA split-bf16 GEMM, 128x128 block tile, K=256 in 8 chunks of 32.
// Round-6 pipeline (STS A ; wait B ; bar ; issue B(kc+1)+LDG A(kc+1) ; MMA).
// Inner loop: N-fragments processed in PAIRS with MMA issue interleaved so
// consecutive MMAs never share an accumulator (reuse distance 1 -> 4), which
// converts the HMMA RAW-latency chain into throughput-limited issue.
// 8 warps in 4(M) x 2(N); each warp computes 32x64 via m16n8k16 bf16 mma.
// 3 products per (mi,ni,k16): Ah*Bh + Ah*Bl + Al*Bh  (fp32 accumulate).
// EDGE=0: writes Q/K/V.  EDGE=1: per-edge head-score epilogue -> g_S.
// ---------------------------------------------------------------------------
template<int EDGE>
__global__ void __launch_bounds__(256, 2) mma_gemm_kernel(const float* __restrict__ Asrc) {
    extern __shared__ __align__(16) char dsm[];
    __shared__ int Ssrc[128], Sdst[128];

    const int tid  = threadIdx.x;
    const int wid  = tid >> 5;
    const int lane = tid & 31;
    const int wm   = wid & 3;
    const int wn   = wid >> 2;
    const int quad = lane & 3;
    const int qrow = lane >> 2;

    const int row0  = blockIdx.x * 128;
    const int nbase = blockIdx.y * 128;
    const int Mtot  = EDGE ? NE : NN;

    if (EDGE && tid < 128) {
        int ge = row0 + tid;
        if (ge > NE - 1) ge = NE - 1;
        Ssrc[tid] = g_src[ge];
        Sdst[tid] = g_dst[ge];
    }

    const float4* A4 = (const float4*)Asrc;
    const uint4* Bh4 = EDGE ? (const uint4*)g_WEh : (const uint4*)g_Wh;
    const uint4* Bl4 = EDGE ? (const uint4*)g_WEl : (const uint4*)g_Wl;

    float acc[2][8][4] = {};

    const uint32_t base = smem_u32(dsm);
    const uint32_t aOff = (uint32_t)((wm * 32 + (lane & 15)) * 80 + (lane >> 4) * 16);
    const uint32_t bOffRow = (uint32_t)((wn * 64 + (lane & 7)) * 80 + ((lane >> 3) & 1) * 16);

    // Per-thread fixed staging coords.
    const int aRow[4] = { (tid + 0) >> 3, (tid + 256) >> 3, (tid + 512) >> 3, (tid + 768) >> 3 };
    const int aC4 = tid & 7;
    long aRowG[4];
    #pragma unroll
    for (int l = 0; l < 4; ++l) aRowG[l] = min(row0 + aRow[l], Mtot - 1);

    // ---- prologue: prefetch A(0) regs; issue cp.async B(0) -> stage 0 ----
    float4 aPre[4];
    #pragma unroll
    for (int l = 0; l < 4; ++l) aPre[l] = A4[aRowG[l] * 64 + 0 + aC4];
    {
        uint32_t bB = base + B_BASE;   // stage 0
        #pragma unroll
        for (int l = 0; l < 4; ++l) {
            int idx = tid + l * 256;
            int sel = idx >> 9;
            int w   = idx & 511;
            int row = w >> 2;
            int c4  = w & 3;
            const uint4* gsrc = (sel ? Bl4 : Bh4) + (long)(nbase + row) * 32 + 0 + c4;
            cp_async16(bB + (uint32_t)(sel * HALF_BYTES + row * 80 + c4 * 16), gsrc);
        }
        cp_commit();
    }

    for (int kc = 0; kc < 8; ++kc) {
        const int st = kc & 1;
        const uint32_t aBase = base + st * STAGE_BYTES;
        const uint32_t bBase = base + B_BASE + st * STAGE_BYTES;

        // STS A(kc) into stage st (readers of this stage finished at sync(kc-1)).
        stsA(dsm + st * STAGE_BYTES, aPre, aRow, aC4);

        cp_wait0();        // B(kc) landed (issued a full iteration ago)
        __syncthreads();   // all warps done with MMA(kc-1); stages coherent

        // Issue B(kc+1) into the other stage; prefetch A(kc+1) regs.
        if (kc < 7) {
            uint32_t bBn = base + B_BASE + (st ^ 1) * STAGE_BYTES;
            #pragma unroll
            for (int l = 0; l < 4; ++l) {
                int idx = tid + l * 256;
                int sel = idx >> 9;
                int w   = idx & 511;
                int row = w >> 2;
                int c4  = w & 3;
                const uint4* gsrc = (sel ? Bl4 : Bh4) + (long)(nbase + row) * 32 + (kc + 1) * 4 + c4;
                cp_async16(bBn + (uint32_t)(sel * HALF_BYTES + row * 80 + c4 * 16), gsrc);
            }
            cp_commit();
            #pragma unroll
            for (int l = 0; l < 4; ++l)
                aPre[l] = A4[aRowG[l] * 64 + (kc + 1) * 8 + aC4];
        }

        // ---- MMA on stage st: ni in pairs, interleaved accumulators ----
        #pragma unroll
        for (int s = 0; s < 2; ++s) {
            uint32_t ah[2][4], al[2][4];
            #pragma unroll
            for (int mi = 0; mi < 2; ++mi) {
                uint32_t o = aOff + (uint32_t)(mi * 16 * 80 + s * 32);
                ldsm_x4(ah[mi], aBase + o);
                ldsm_x4(al[mi], aBase + HALF_BYTES + o);
            }
            #pragma unroll
            for (int nj = 0; nj < 4; ++nj) {
                const int ni = nj * 2;
                uint32_t bo0 = bOffRow + (uint32_t)((ni + 0) * 8 * 80 + s * 32);
                uint32_t bo1 = bOffRow + (uint32_t)((ni + 1) * 8 * 80 + s * 32);
                uint32_t bh0[2], bl0[2], bh1[2], bl1[2];
                ldsm_x2(bh0, bBase + bo0);
                ldsm_x2(bh1, bBase + bo1);
                ldsm_x2(bl0, bBase + HALF_BYTES + bo0);
                ldsm_x2(bl1, bBase + HALF_BYTES + bo1);
                // 12 MMAs; same-acc reuse distance = 4 issue slots.
                mma_bf16(acc[0][ni],     ah[0], bh0);
                mma_bf16(acc[0][ni + 1], ah[0], bh1);
                mma_bf16(acc[1][ni],     ah[1], bh0);
                mma_bf16(acc[1][ni + 1], ah[1], bh1);
                mma_bf16(acc[0][ni],     ah[0], bl0);
                mma_bf16(acc[0][ni + 1], ah[0], bl1);
                mma_bf16(acc[1][ni],     ah[1], bl0);
                mma_bf16(acc[1][ni + 1], ah[1], bl1);
                mma_bf16(acc[0][ni],     al[0], bh0);
                mma_bf16(acc[0][ni + 1], al[0], bh1);
                mma_bf16(acc[1][ni],     al[1], bh0);
                mma_bf16(acc[1][ni + 1], al[1], bh1);
            }
        }
    }

    if (EDGE) {
        // Per-edge head scores for this tile's 4 heads -> g_S.
        const float scale = 0.17677669529663687f;  // 1/sqrt(32)
        #pragma unroll
        for (int mi = 0; mi < 2; ++mi) {
            #pragma unroll
            for (int rh = 0; rh < 2; ++rh) {
                int r  = wm * 32 + mi * 16 + qrow + rh * 8;
                int ge = row0 + r;
                const float* Kr = g_K + (long)Ssrc[r] * DIMC + nbase + wn * 64;
                const float* Qr = g_Q + (long)Sdst[r] * DIMC + nbase + wn * 64;
                #pragma unroll
                for (int h = 0; h < 2; ++h) {
                    float p = 0.0f;
                    #pragma unroll
                    for (int j = 0; j < 4; ++j) {
                        int ni = h * 4 + j;
                        int c  = ni * 8 + quad * 2;
                        float2 kv = *(const float2*)(Kr + c);
                        float2 qv = *(const float2*)(Qr + c);
                        p += acc[mi][ni][rh * 2 + 0] * kv.x * qv.x;
                        p += acc[mi][ni][rh * 2 + 1] * kv.y * qv.y;
                    }
                    p += __shfl_xor_sync(0xffffffffu, p, 1);
                    p += __shfl_xor_sync(0xffffffffu, p, 2);
                    if (quad == 0 && ge < NE) {
                        float sv = fminf(5.0f, fmaxf(-5.0f, p * scale));
                        g_S[(long)ge * NH + (nbase >> 5) + wn * 2 + h] = expf(sv);
                    }
                }
            }
        }
    } else {
        int by = blockIdx.y;
        float* Cout = (by < 2) ? g_Q : (by < 4) ? g_K : g_V;
        int colb = (by & 1) * 128;
        #pragma unroll
        for (int mi = 0; mi < 2; ++mi) {
            #pragma unroll
            for (int ni = 0; ni < 8; ++ni) {
                int r = row0 + wm * 32 + mi * 16 + qrow;
                int c = colb + wn * 64 + ni * 8 + quad * 2;
                if (r < NN)
                    *(float2*)(Cout + (long)r * DIMC + c) =
                        make_float2(acc[mi][ni][0], acc[mi][ni][1]);
                if (r + 8 < NN)
                    *(float2*)(Cout + (long)(r + 8) * DIMC + c) =
                        make_float2(acc[mi][ni][2], acc[mi][ni][3]);
            }
        }
    }
}

// ---------------------------------------------------------------------------
// Scatter: wV[dst] += V[src]*score ; Z[dst,h] += score.  32 edges per block.
// (round-6 version: 1 column/thread, max RED parallelism)
// ---------------------------------------------------------------------------
__global__ void scatter_kernel() {
    __shared__ int ssrc[32], sdst[32];
    __shared__ float ssc[32][NH];
    int e0 = blockIdx.x * 32;
    int tid = threadIdx.x;
    if (tid < 32) {
        int ge = e0 + tid;
        ssrc[tid] = (ge < NE) ? g_src[ge] : 0;
        sdst[tid] = (ge < NE) ? g_dst[ge] : 0;
    }
    {
        int el = tid >> 3, h = tid & 7;
        int ge = e0 + el;
        ssc[el][h] = (ge < NE) ? g_S[(long)ge * NH + h] : 0.0f;
    }
    __syncthreads();
    int c = tid;
    int h = c >> 5;
    for (int el = 0; el < 32; ++el) {
        int ge = e0 + el;
        if (ge >= NE) break;
        float s = ssc[el][h];
        atomicAdd(&g_wV[(long)sdst[el] * DIMC + c], g_V[(long)ssrc[el] * DIMC + c] * s);
    }
    {
        int el = tid >> 3, h2 = tid & 7;
        int ge = e0 + el;
        if (ge < NE) atomicAdd(&g_Z[(long)sdst[el] * NH + h2], ssc[el][h2]);
    }
}

// ---------------------------------------------------------------------------
// Residual + BN column stats, then normalize.
// ---------------------------------------------------------------------------
__global__ void resid_stats_kernel(const float* __restrict__ x, float* __restrict__ out) {
    int c = threadIdx.x;
    int r0 = blockIdx.x * 256;
    int rend = min(NN, r0 + 256);
    float s = 0.0f, s2 = 0.0f;
    for (int n = r0; n < rend; ++n) {
        float z = g_Z[(long)n * NH + (c >> 5)] + 1e-6f;
        float h = x[(long)n * DIMC + c] + g_wV[(long)n * DIMC + c] / z;
        out[(long)n * DIMC + c] = h;
        s += h;
        s2 += h * h;
    }
    atomicAdd(&g_cs[c], s);
    atomicAdd(&g_cs2[c], s2);
}

__global__ void bn_norm_kernel(float* __restrict__ out,
                               const float* __restrict__ gamma,
                               const float* __restrict__ beta) {
    long total = (long)NN * DIMC;
    long stride = (long)gridDim.x * blockDim.x;
    const float invN = 1.0f / (float)NN;
    for (long i = (long)blockIdx.x * blockDim.x + threadIdx.x; i < total; i += stride) {
        int c = (int)(i & (DIMC - 1));
        float mean = g_cs[c] * invN;
        float var = g_cs2[c] * invN - mean * mean;
        out[i] = (out[i] - mean) * rsqrtf(var + 1e-5f) * gamma[c] + beta[c];
    }
}

extern "C" void kernel_launch(void* const* d_in, const int* in_sizes, int n_in,
                              void* d_out, int out_size) {
    const float* x     = (const float*)d_in[0];
    const float* ea    = (const float*)d_in[1];
    const float* WQ    = (const float*)d_in[2];
    const float* WK    = (const float*)d_in[3];
    const float* WE    = (const float*)d_in[4];
    const float* WV    = (const float*)d_in[5];
    const float* gamma = (const float*)d_in[6];
    const float* beta  = (const float*)d_in[7];
    const long long* eidx = (const long long*)d_in[8];
    float* out = (float*)d_out;

    // Opt-in to >48KB dynamic smem (attribute set, not an allocation).
    cudaFuncSetAttribute(mma_gemm_kernel<0>,
                         cudaFuncAttributeMaxDynamicSharedMemorySize, DYN_SMEM);
    cudaFuncSetAttribute(mma_gemm_kernel<1>,
                         cudaFuncAttributeMaxDynamicSharedMemorySize, DYN_SMEM);

    zero_kernel<<<1024, 256>>>();
    cvt_idx_kernel<<<512, 256>>>(eidx);
    prep_w_kernel<<<1024, 256>>>(WQ, WK, WV, WE);

    // QKV: C[100000,768] -> 782 x 6 tiles of 128x128 (A = x, converted in-kernel)
    mma_gemm_kernel<0><<<dim3(782, 6), 256, DYN_SMEM>>>(x);
    // Edge: Eh GEMM + fused score epilogue -> 3907 x 2 tiles
    mma_gemm_kernel<1><<<dim3(3907, 2), 256, DYN_SMEM>>>(ea);

    scatter_kernel<<<(NE + 31) / 32, 256>>>();
    resid_stats_kernel<<<(NN + 255) / 256, 256>>>(x, out);
    bn_norm_kernel<<<2048, 256>>>(out, gamma, beta);
}

// round 9
// speedup vs baseline: 1.1642x; 1.0251x over previous
#include <cuda_runtime.h>
#include <cuda_bf16.h>
#include <math.h>
#include <stdint.h>

#define NN 100000
#define NE 500000
#define DIMC 256
#define NH 8

// Dynamic smem layout (bytes):
//   A stage s (s=0,1): base + s*20480   -> Ah at +0, Al at +10240
//   B stage s:         base + 40960 + s*20480 -> Bh at +0, Bl at +10240
#define STAGE_BYTES 20480
#define HALF_BYTES  10240
#define B_BASE      40960
#define DYN_SMEM    81920

// ---------------------------------------------------------------------------
// Device-global scratch (no allocation allowed in kernel_launch)
// ---------------------------------------------------------------------------
__device__ float g_Q[NN * DIMC];
__device__ float g_K[NN * DIMC];
__device__ float g_V[NN * DIMC];
__device__ float g_wV[NN * DIMC];
__device__ float g_Z[NN * NH];
__device__ float g_S[NE * NH];
__device__ float g_cs[DIMC];
__device__ float g_cs2[DIMC];
__device__ int g_src[NE];
__device__ int g_dst[NE];
__device__ __nv_bfloat16 g_Wh[768 * DIMC], g_Wl[768 * DIMC];     // [n][k], QKV concat
__device__ __nv_bfloat16 g_WEh[DIMC * DIMC], g_WEl[DIMC * DIMC]; // [n][k]

// ---------------------------------------------------------------------------
// Warp-MMA helpers (portable PTX: ldmatrix + mma.sync + cp.async, sm_80+)
// ---------------------------------------------------------------------------
__device__ __forceinline__ uint32_t smem_u32(const void* p) {
    uint32_t a;
    asm("{ .reg .u64 t; cvta.to.shared.u64 t, %1; cvt.u32.u64 %0, t; }"
        : "=r"(a) : "l"(p));
    return a;
}
__device__ __forceinline__ void ldsm_x4(uint32_t* r, uint32_t addr) {
    asm volatile("ldmatrix.sync.aligned.m8n8.x4.shared.b16 {%0,%1,%2,%3}, [%4];"
                 : "=r"(r[0]), "=r"(r[1]), "=r"(r[2]), "=r"(r[3]) : "r"(addr));
}
__device__ __forceinline__ void ldsm_x2(uint32_t* r, uint32_t addr) {
    asm volatile("ldmatrix.sync.aligned.m8n8.x2.shared.b16 {%0,%1}, [%2];"
                 : "=r"(r[0]), "=r"(r[1]) : "r"(addr));
}
__device__ __forceinline__ void mma_bf16(float* d, const uint32_t* a, const uint32_t* b) {
    asm volatile(
        "mma.sync.aligned.m16n8k16.row.col.f32.bf16.bf16.f32 "
        "{%0,%1,%2,%3}, {%4,%5,%6,%7}, {%8,%9}, {%0,%1,%2,%3};"
        : "+f"(d[0]), "+f"(d[1]), "+f"(d[2]), "+f"(d[3])
        : "r"(a[0]), "r"(a[1]), "r"(a[2]), "r"(a[3]), "r"(b[0]), "r"(b[1]));
}
__device__ __forceinline__ void cp_async16(uint32_t saddr, const void* gptr) {
    asm volatile("cp.async.cg.shared.global [%0], [%1], 16;"
                 :: "r"(saddr), "l"(gptr) : "memory");
}
__device__ __forceinline__ void cp_commit() {
    asm volatile("cp.async.commit_group;" ::: "memory");
}
__device__ __forceinline__ void cp_wait0() {
    asm volatile("cp.async.wait_group 0;" ::: "memory");
}
// Vectorized global fp32 reduction (sm_90+): 4 adds in one instruction.
__device__ __forceinline__ void red_v4(float* gptr, float4 v) {
    asm volatile("red.global.add.v4.f32 [%0], {%1, %2, %3, %4};"
                 :: "l"(gptr), "f"(v.x), "f"(v.y), "f"(v.z), "f"(v.w) : "memory");
}

// ---------------------------------------------------------------------------
// Zero atomically-updated accumulators.
// ---------------------------------------------------------------------------
__global__ void zero_kernel() {
    long total = (long)NN * DIMC + (long)NN * NH;
    long stride = (long)gridDim.x * blockDim.x;
    for (long i = (long)blockIdx.x * blockDim.x + threadIdx.x; i < total; i += stride) {
        if (i < (long)NN * DIMC) g_wV[i] = 0.0f;
        else                     g_Z[i - (long)NN * DIMC] = 0.0f;
    }
    if (blockIdx.x == 0 && threadIdx.x < DIMC) {
        g_cs[threadIdx.x]  = 0.0f;
        g_cs2[threadIdx.x] = 0.0f;
    }
}

// ---------------------------------------------------------------------------
// edge_index -> int32 src/dst (handles int64 or int32 payload, deterministic)
// ---------------------------------------------------------------------------
__global__ void cvt_idx_kernel(const long long* __restrict__ e64) {
    const int* e32 = (const int*)e64;
    bool is64 = true;
    #pragma unroll
    for (int i = 0; i < 64; ++i)
        if ((e64[i] >> 32) != 0) is64 = false;
    long stride = (long)gridDim.x * blockDim.x;
    for (long e = (long)blockIdx.x * blockDim.x + threadIdx.x; e < NE; e += stride) {
        if (is64) { g_src[e] = (int)e64[e]; g_dst[e] = (int)e64[NE + e]; }
        else      { g_src[e] = e32[e];      g_dst[e] = e32[NE + e];      }
    }
}

// ---------------------------------------------------------------------------
// Weights transposed into B-operand layout [n][k], split hi/lo. (Tiny.)
// ---------------------------------------------------------------------------
__global__ void prep_w_kernel(const float* __restrict__ WQ, const float* __restrict__ WK,
                              const float* __restrict__ WV, const float* __restrict__ WE) {
    int i = blockIdx.x * 256 + threadIdx.x;   // 0 .. 1024*256-1
    if (i < 768 * DIMC) {
        int n = i >> 8;
        int k = i & 255;
        int m = n >> 8, nn = n & 255;
        const float* W = (m == 0) ? WQ : (m == 1) ? WK : WV;
        float v = W[k * DIMC + nn];
        __nv_bfloat16 h = __float2bfloat16(v);
        g_Wh[i] = h;
        g_Wl[i] = __float2bfloat16(v - __bfloat162float(h));
    } else {
        int j = i - 768 * DIMC;
        int n = j >> 8, k = j & 255;
        float v = WE[k * DIMC + n];
        __nv_bfloat16 h = __float2bfloat16(v);
        g_WEh[j] = h;
        g_WEl[j] = __float2bfloat16(v - __bfloat162float(h));
    }
}

// ---------------------------------------------------------------------------
// Convert & store one A chunk (4 float4 per thread) to hi/lo bf16 smem stage.
// ---------------------------------------------------------------------------
__device__ __forceinline__ void stsA(char* stage, const float4* v4,
                                     const int* aRow, int aC4) {
    __nv_bfloat16* sAh = (__nv_bfloat16*)stage;
    __nv_bfloat16* sAl = (__nv_bfloat16*)(stage + HALF_BYTES);
    #pragma unroll
    for (int l = 0; l < 4; ++l) {
        float4 v = v4[l];
        __nv_bfloat162 h01 = __floats2bfloat162_rn(v.x, v.y);
        __nv_bfloat162 h23 = __floats2bfloat162_rn(v.z, v.w);
        __nv_bfloat162 l01 = __floats2bfloat162_rn(v.x - __low2float(h01),
                                                   v.y - __high2float(h01));
        __nv_bfloat162 l23 = __floats2bfloat162_rn(v.z - __low2float(h23),
                                                   v.w - __high2float(h23));
        int row = aRow[l];
        *(uint2*)(sAh + row * 40 + aC4 * 4) =
            make_uint2(*(uint32_t*)&h01, *(uint32_t*)&h23);
        *(uint2*)(sAl + row * 40 + aC4 * 4) =
            make_uint2(*(uint32_t*)&l01, *(uint32_t*)&l23);
    }
}

// ---------------------------------------------------------------------------
// Warp-MMA split-bf16 GEMM, 128x128 block tile, K=256 in 8 chunks of 32.
// Grid: x = N-tile (fast-varying -> CTAs sharing A rows are schedule-adjacent
// for L2 reuse of A), y = row-tile.
// Pipeline per iter: STS A ; wait B ; bar ; issue B(kc+1)+LDG A(kc+1) ; MMA.
// Inner loop: N-fragments in pairs with interleaved accumulators.
// 3 products per (mi,ni,k16): Ah*Bh + Ah*Bl + Al*Bh  (fp32 accumulate).
// EDGE=0: writes Q/K/V.  EDGE=1: per-edge head-score epilogue -> g_S.
// ---------------------------------------------------------------------------
template<int EDGE>
__global__ void __launch_bounds__(256, 2) mma_gemm_kernel(const float* __restrict__ Asrc) {
    extern __shared__ __align__(16) char dsm[];
    __shared__ int Ssrc[128], Sdst[128];

    const int tid  = threadIdx.x;
    const int wid  = tid >> 5;
    const int lane = tid & 31;
    const int wm   = wid & 3;
    const int wn   = wid >> 2;
    const int quad = lane & 3;
    const int qrow = lane >> 2;

    const int row0  = blockIdx.y * 128;
    const int nbase = blockIdx.x * 128;
    const int Mtot  = EDGE ? NE : NN;

    if (EDGE && tid < 128) {
        int ge = row0 + tid;
        if (ge > NE - 1) ge = NE - 1;
        Ssrc[tid] = g_src[ge];
        Sdst[tid] = g_dst[ge];
    }

    const float4* A4 = (const float4*)Asrc;
    const uint4* Bh4 = EDGE ? (const uint4*)g_WEh : (const uint4*)g_Wh;
    const uint4* Bl4 = EDGE ? (const uint4*)g_WEl : (const uint4*)g_Wl;

    float acc[2][8][4] = {};

    const uint32_t base = smem_u32(dsm);
    const uint32_t aOff = (uint32_t)((wm * 32 + (lane & 15)) * 80 + (lane >> 4) * 16);
    const uint32_t bOffRow = (uint32_t)((wn * 64 + (lane & 7)) * 80 + ((lane >> 3) & 1) * 16);

    // Per-thread fixed staging coords.
    const int aRow[4] = { (tid + 0) >> 3, (tid + 256) >> 3, (tid + 512) >> 3, (tid + 768) >> 3 };
    const int aC4 = tid & 7;
    long aRowG[4];
    #pragma unroll
    for (int l = 0; l < 4; ++l) aRowG[l] = min(row0 + aRow[l], Mtot - 1);

    // ---- prologue: prefetch A(0) regs; issue cp.async B(0) -> stage 0 ----
    float4 aPre[4];
    #pragma unroll
    for (int l = 0; l < 4; ++l) aPre[l] = A4[aRowG[l] * 64 + 0 + aC4];
    {
        uint32_t bB = base + B_BASE;   // stage 0
        #pragma unroll
        for (int l = 0; l < 4; ++l) {
            int idx = tid + l * 256;
            int sel = idx >> 9;
            int w   = idx & 511;
            int row = w >> 2;
            int c4  = w & 3;
            const uint4* gsrc = (sel ? Bl4 : Bh4) + (long)(nbase + row) * 32 + 0 + c4;
            cp_async16(bB + (uint32_t)(sel * HALF_BYTES + row * 80 + c4 * 16), gsrc);
        }
        cp_commit();
    }

    for (int kc = 0; kc < 8; ++kc) {
        const int st = kc & 1;
        const uint32_t aBase = base + st * STAGE_BYTES;
        const uint32_t bBase = base + B_BASE + st * STAGE_BYTES;

        // STS A(kc) into stage st (readers of this stage finished at sync(kc-1)).
        stsA(dsm + st * STAGE_BYTES, aPre, aRow, aC4);

        cp_wait0();        // B(kc) landed (issued a full iteration ago)
        __syncthreads();   // all warps done with MMA(kc-1); stages coherent

        // Issue B(kc+1) into the other stage; prefetch A(kc+1) regs.
        if (kc < 7) {
            uint32_t bBn = base + B_BASE + (st ^ 1) * STAGE_BYTES;
            #pragma unroll
            for (int l = 0; l < 4; ++l) {
                int idx = tid + l * 256;
                int sel = idx >> 9;
                int w   = idx & 511;
                int row = w >> 2;
                int c4  = w & 3;
                const uint4* gsrc = (sel ? Bl4 : Bh4) + (long)(nbase + row) * 32 + (kc + 1) * 4 + c4;
                cp_async16(bBn + (uint32_t)(sel * HALF_BYTES + row * 80 + c4 * 16), gsrc);
            }
            cp_commit();
            #pragma unroll
            for (int l = 0; l < 4; ++l)
                aPre[l] = A4[aRowG[l] * 64 + (kc + 1) * 8 + aC4];
        }

        // ---- MMA on stage st: ni in pairs, interleaved accumulators ----
        #pragma unroll
        for (int s = 0; s < 2; ++s) {
            uint32_t ah[2][4], al[2][4];
            #pragma unroll
            for (int mi = 0; mi < 2; ++mi) {
                uint32_t o = aOff + (uint32_t)(mi * 16 * 80 + s * 32);
                ldsm_x4(ah[mi], aBase + o);
                ldsm_x4(al[mi], aBase + HALF_BYTES + o);
            }
            #pragma unroll
            for (int nj = 0; nj < 4; ++nj) {
                const int ni = nj * 2;
                uint32_t bo0 = bOffRow + (uint32_t)((ni + 0) * 8 * 80 + s * 32);
                uint32_t bo1 = bOffRow + (uint32_t)((ni + 1) * 8 * 80 + s * 32);
                uint32_t bh0[2], bl0[2], bh1[2], bl1[2];
                ldsm_x2(bh0, bBase + bo0);
                ldsm_x2(bh1, bBase + bo1);
                ldsm_x2(bl0, bBase + HALF_BYTES + bo0);
                ldsm_x2(bl1, bBase + HALF_BYTES + bo1);
                // 12 MMAs; same-acc reuse distance = 4 issue slots.
                mma_bf16(acc[0][ni],     ah[0], bh0);
                mma_bf16(acc[0][ni + 1], ah[0], bh1);
                mma_bf16(acc[1][ni],     ah[1], bh0);
                mma_bf16(acc[1][ni + 1], ah[1], bh1);
                mma_bf16(acc[0][ni],     ah[0], bl0);
                mma_bf16(acc[0][ni + 1], ah[0], bl1);
                mma_bf16(acc[1][ni],     ah[1], bl0);
                mma_bf16(acc[1][ni + 1], ah[1], bl1);
                mma_bf16(acc[0][ni],     al[0], bh0);
                mma_bf16(acc[0][ni + 1], al[0], bh1);
                mma_bf16(acc[1][ni],     al[1], bh0);
                mma_bf16(acc[1][ni + 1], al[1], bh1);
            }
        }
    }

    if (EDGE) {
        // Per-edge head scores for this tile's 4 heads -> g_S.
        const float scale = 0.17677669529663687f;  // 1/sqrt(32)
        #pragma unroll
        for (int mi = 0; mi < 2; ++mi) {
            #pragma unroll
            for (int rh = 0; rh < 2; ++rh) {
                int r  = wm * 32 + mi * 16 + qrow + rh * 8;
                int ge = row0 + r;
                const float* Kr = g_K + (long)Ssrc[r] * DIMC + nbase + wn * 64;
                const float* Qr = g_Q + (long)Sdst[r] * DIMC + nbase + wn * 64;
                #pragma unroll
                for (int h = 0; h < 2; ++h) {
                    float p = 0.0f;
                    #pragma unroll
                    for (int j = 0; j < 4; ++j) {
                        int ni = h * 4 + j;
                        int c  = ni * 8 + quad * 2;
                        float2 kv = *(const float2*)(Kr + c);
                        float2 qv = *(const float2*)(Qr + c);
                        p += acc[mi][ni][rh * 2 + 0] * kv.x * qv.x;
                        p += acc[mi][ni][rh * 2 + 1] * kv.y * qv.y;
                    }
                    p += __shfl_xor_sync(0xffffffffu, p, 1);
                    p += __shfl_xor_sync(0xffffffffu, p, 2);
                    if (quad == 0 && ge < NE) {
                        float sv = fminf(5.0f, fmaxf(-5.0f, p * scale));
                        g_S[(long)ge * NH + (nbase >> 5) + wn * 2 + h] = expf(sv);
                    }
                }
            }
        }
    } else {
        int bx = blockIdx.x;
        float* Cout = (bx < 2) ? g_Q : (bx < 4) ? g_K : g_V;
        int colb = (bx & 1) * 128;
        #pragma unroll
        for (int mi = 0; mi < 2; ++mi) {
            #pragma unroll
            for (int ni = 0; ni < 8; ++ni) {
                int r = row0 + wm * 32 + mi * 16 + qrow;
                int c = colb + wn * 64 + ni * 8 + quad * 2;
                if (r < NN)
                    *(float2*)(Cout + (long)r * DIMC + c) =
                        make_float2(acc[mi][ni][0], acc[mi][ni][1]);
                if (r + 8 < NN)
                    *(float2*)(Cout + (long)(r + 8) * DIMC + c) =
                        make_float2(acc[mi][ni][2], acc[mi][ni][3]);
            }
        }
    }
}

// ---------------------------------------------------------------------------
// Scatter: wV[dst] += V[src]*score ; Z[dst,h] += score.  32 edges per block.
// Vectorized red.global.add.v4.f32: thread t covers column group (t&63)*4,
// edges (t>>6)*8 .. +7.  For fixed i, threads 0..63 sweep a full V row
// (64 float4 = 1KB, coalesced).  Z: 2 v4 reds per edge.
// ---------------------------------------------------------------------------
__global__ void scatter_kernel() {
    __shared__ int ssrc[32], sdst[32];
    __shared__ __align__(16) float ssc[32][NH];
    int e0 = blockIdx.x * 32;
    int tid = threadIdx.x;
    if (tid < 32) {
        int ge = e0 + tid;
        ssrc[tid] = (ge < NE) ? g_src[ge] : 0;
        sdst[tid] = (ge < NE) ? g_dst[ge] : 0;
    }
    {
        int el = tid >> 3, h = tid & 7;
        int ge = e0 + el;
        ssc[el][h] = (ge < NE) ? g_S[(long)ge * NH + h] : 0.0f;
    }
    __syncthreads();
    int cg = (tid & 63) * 4;        // column 0..252 step 4
    int h  = cg >> 5;               // head of this column group
    int ebeg = (tid >> 6) * 8;      // 4 edge groups of 8
    #pragma unroll
    for (int i = 0; i < 8; ++i) {
        int el = ebeg + i;
        int ge = e0 + el;
        if (ge < NE) {
            float s = ssc[el][h];
            float4 v = *(const float4*)(g_V + (long)ssrc[el] * DIMC + cg);
            v.x *= s; v.y *= s; v.z *= s; v.w *= s;
            red_v4(g_wV + (long)sdst[el] * DIMC + cg, v);
        }
    }
    if (tid < 64) {
        int el = tid >> 1, half = tid & 1;
        int ge = e0 + el;
        if (ge < NE) {
            float4 z = *(const float4*)(&ssc[el][half * 4]);
            red_v4(g_Z + (long)sdst[el] * NH + half * 4, z);
        }
    }
}

// ---------------------------------------------------------------------------
// Residual + BN column stats, then normalize.
// ---------------------------------------------------------------------------
__global__ void resid_stats_kernel(const float* __restrict__ x, float* __restrict__ out) {
    int c = threadIdx.x;
    int r0 = blockIdx.x * 256;
    int rend = min(NN, r0 + 256);
    float s = 0.0f, s2 = 0.0f;
    for (int n = r0; n < rend; ++n) {
        float z = g_Z[(long)n * NH + (c >> 5)] + 1e-6f;
        float h = x[(long)n * DIMC + c] + g_wV[(long)n * DIMC + c] / z;
        out[(long)n * DIMC + c] = h;
        s += h;
        s2 += h * h;
    }
    atomicAdd(&g_cs[c], s);
    atomicAdd(&g_cs2[c], s2);
}

__global__ void bn_norm_kernel(float* __restrict__ out,
                               const float* __restrict__ gamma,
                               const float* __restrict__ beta) {
    long total = (long)NN * DIMC;
    long stride = (long)gridDim.x * blockDim.x;
    const float invN = 1.0f / (float)NN;
    for (long i = (long)blockIdx.x * blockDim.x + threadIdx.x; i < total; i += stride) {
        int c = (int)(i & (DIMC - 1));
        float mean = g_cs[c] * invN;
        float var = g_cs2[c] * invN - mean * mean;
        out[i] = (out[i] - mean) * rsqrtf(var + 1e-5f) * gamma[c] + beta[c];
    }
}

extern "C" void kernel_launch(void* const* d_in, const int* in_sizes, int n_in,
                              void* d_out, int out_size) {
    const float* x     = (const float*)d_in[0];
    const float* ea    = (const float*)d_in[1];
    const float* WQ    = (const float*)d_in[2];
    const float* WK    = (const float*)d_in[3];
    const float* WE    = (const float*)d_in[4];
    const float* WV    = (const float*)d_in[5];
    const float* gamma = (const float*)d_in[6];
    const float* beta  = (const float*)d_in[7];
    const long long* eidx = (const long long*)d_in[8];
    float* out = (float*)d_out;

    // Opt-in to >48KB dynamic smem (attribute set, not an allocation).
    cudaFuncSetAttribute(mma_gemm_kernel<0>,
                         cudaFuncAttributeMaxDynamicSharedMemorySize, DYN_SMEM);
    cudaFuncSetAttribute(mma_gemm_kernel<1>,
                         cudaFuncAttributeMaxDynamicSharedMemorySize, DYN_SMEM);

    zero_kernel<<<1024, 256>>>();
    cvt_idx_kernel<<<512, 256>>>(eidx);
    prep_w_kernel<<<1024, 256>>>(WQ, WK, WV, WE);

    // QKV: x = N-tile (6), y = row-tile (782) -> schedule-adjacent CTAs share A.
    mma_gemm_kernel<0><<<dim3(6, 782), 256, DYN_SMEM>>>(x);
    // Edge: x = N-tile (2), y = row-tile (3907).
    mma_gemm_kernel<1><<<dim3(2, 3907), 256, DYN_SMEM>>>(ea);

    scatter_kernel<<<(NE + 31) / 32, 256>>>();
    resid_stats_kernel<<<(NN + 255) / 256, 256>>>(x, out);
    bn_norm_kernel<<<2048, 256>>>(out, gamma, beta);
}

// round 10
// speedup vs baseline: 1.1743x; 1.0087x over previous
#include <cuda_runtime.h>
#include <cuda_bf16.h>
#include <math.h>
#include <stdint.h>

#define NN 100000
#define NE 500000
#define DIMC 256
#define NH 8

// Dynamic smem layout (bytes):
//   A stage s (s=0,1): base + s*20480   -> Ah at +0, Al at +10240
//   B stage s:         base + 40960 + s*20480 -> Bh at +0, Bl at +10240
#define STAGE_BYTES 20480
#define HALF_BYTES  10240
#define B_BASE      40960
#define DYN_SMEM    81920

// ---------------------------------------------------------------------------
// Device-global scratch (no allocation allowed in kernel_launch)
// ---------------------------------------------------------------------------
__device__ float g_Q[NN * DIMC];
__device__ float g_K[NN * DIMC];
__device__ float g_V[NN * DIMC];
__device__ float g_wV[NN * DIMC];
__device__ float g_Z[NN * NH];
__device__ float g_S[NE * NH];
__device__ float g_cs[DIMC];
__device__ float g_cs2[DIMC];
__device__ int g_src[NE];
__device__ int g_dst[NE];
__device__ __nv_bfloat16 g_Wh[768 * DIMC], g_Wl[768 * DIMC];     // [n][k], QKV concat
__device__ __nv_bfloat16 g_WEh[DIMC * DIMC], g_WEl[DIMC * DIMC]; // [n][k]

// ---------------------------------------------------------------------------
// Warp-MMA helpers (portable PTX: ldmatrix + mma.sync + cp.async, sm_80+)
// ---------------------------------------------------------------------------
__device__ __forceinline__ uint32_t smem_u32(const void* p) {
    uint32_t a;
    asm("{ .reg .u64 t; cvta.to.shared.u64 t, %1; cvt.u32.u64 %0, t; }"
        : "=r"(a) : "l"(p));
    return a;
}
__device__ __forceinline__ void ldsm_x4(uint32_t* r, uint32_t addr) {
    asm volatile("ldmatrix.sync.aligned.m8n8.x4.shared.b16 {%0,%1,%2,%3}, [%4];"
                 : "=r"(r[0]), "=r"(r[1]), "=r"(r[2]), "=r"(r[3]) : "r"(addr));
}
__device__ __forceinline__ void mma_bf16(float* d, const uint32_t* a, const uint32_t* b) {
    asm volatile(
        "mma.sync.aligned.m16n8k16.row.col.f32.bf16.bf16.f32 "
        "{%0,%1,%2,%3}, {%4,%5,%6,%7}, {%8,%9}, {%0,%1,%2,%3};"
        : "+f"(d[0]), "+f"(d[1]), "+f"(d[2]), "+f"(d[3])
        : "r"(a[0]), "r"(a[1]), "r"(a[2]), "r"(a[3]), "r"(b[0]), "r"(b[1]));
}
__device__ __forceinline__ void cp_async16(uint32_t saddr, const void* gptr) {
    asm volatile("cp.async.cg.shared.global [%0], [%1], 16;"
                 :: "r"(saddr), "l"(gptr) : "memory");
}
__device__ __forceinline__ void cp_commit() {
    asm volatile("cp.async.commit_group;" ::: "memory");
}
__device__ __forceinline__ void cp_wait0() {
    asm volatile("cp.async.wait_group 0;" ::: "memory");
}
// Vectorized global fp32 reduction (sm_90+): 4 adds in one instruction.
__device__ __forceinline__ void red_v4(float* gptr, float4 v) {
    asm volatile("red.global.add.v4.f32 [%0], {%1, %2, %3, %4};"
                 :: "l"(gptr), "f"(v.x), "f"(v.y), "f"(v.z), "f"(v.w) : "memory");
}

// ---------------------------------------------------------------------------
// Zero atomically-updated accumulators.
// ---------------------------------------------------------------------------
__global__ void zero_kernel() {
    long total = (long)NN * DIMC + (long)NN * NH;
    long stride = (long)gridDim.x * blockDim.x;
    for (long i = (long)blockIdx.x * blockDim.x + threadIdx.x; i < total; i += stride) {
        if (i < (long)NN * DIMC) g_wV[i] = 0.0f;
        else                     g_Z[i - (long)NN * DIMC] = 0.0f;
    }
    if (blockIdx.x == 0 && threadIdx.x < DIMC) {
        g_cs[threadIdx.x]  = 0.0f;
        g_cs2[threadIdx.x] = 0.0f;
    }
}

// ---------------------------------------------------------------------------
// edge_index -> int32 src/dst (handles int64 or int32 payload, deterministic)
// ---------------------------------------------------------------------------
__global__ void cvt_idx_kernel(const long long* __restrict__ e64) {
    const int* e32 = (const int*)e64;
    bool is64 = true;
    #pragma unroll
    for (int i = 0; i < 64; ++i)
        if ((e64[i] >> 32) != 0) is64 = false;
    long stride = (long)gridDim.x * blockDim.x;
    for (long e = (long)blockIdx.x * blockDim.x + threadIdx.x; e < NE; e += stride) {
        if (is64) { g_src[e] = (int)e64[e]; g_dst[e] = (int)e64[NE + e]; }
        else      { g_src[e] = e32[e];      g_dst[e] = e32[NE + e];      }
    }
}

// ---------------------------------------------------------------------------
// Weights transposed into B-operand layout [n][k], split hi/lo. (Tiny.)
// ---------------------------------------------------------------------------
__global__ void prep_w_kernel(const float* __restrict__ WQ, const float* __restrict__ WK,
                              const float* __restrict__ WV, const float* __restrict__ WE) {
    int i = blockIdx.x * 256 + threadIdx.x;   // 0 .. 1024*256-1
    if (i < 768 * DIMC) {
        int n = i >> 8;
        int k = i & 255;
        int m = n >> 8, nn = n & 255;
        const float* W = (m == 0) ? WQ : (m == 1) ? WK : WV;
        float v = W[k * DIMC + nn];
        __nv_bfloat16 h = __float2bfloat16(v);
        g_Wh[i] = h;
        g_Wl[i] = __float2bfloat16(v - __bfloat162float(h));
    } else {
        int j = i - 768 * DIMC;
        int n = j >> 8, k = j & 255;
        float v = WE[k * DIMC + n];
        __nv_bfloat16 h = __float2bfloat16(v);
        g_WEh[j] = h;
        g_WEl[j] = __float2bfloat16(v - __bfloat162float(h));
    }
}

// ---------------------------------------------------------------------------
// Convert & store one A chunk (4 float4 per thread) to hi/lo bf16 smem stage.
// ---------------------------------------------------------------------------
__device__ __forceinline__ void stsA(char* stage, const float4* v4,
                                     const int* aRow, int aC4) {
    __nv_bfloat16* sAh = (__nv_bfloat16*)stage;
    __nv_bfloat16* sAl = (__nv_bfloat16*)(stage + HALF_BYTES);
    #pragma unroll
    for (int l = 0; l < 4; ++l) {
        float4 v = v4[l];
        __nv_bfloat162 h01 = __floats2bfloat162_rn(v.x, v.y);
        __nv_bfloat162 h23 = __floats2bfloat162_rn(v.z, v.w);
        __nv_bfloat162 l01 = __floats2bfloat162_rn(v.x - __low2float(h01),
                                                   v.y - __high2float(h01));
        __nv_bfloat162 l23 = __floats2bfloat162_rn(v.z - __low2float(h23),
                                                   v.w - __high2float(h23));
        int row = aRow[l];
        *(uint2*)(sAh + row * 40 + aC4 * 4) =
            make_uint2(*(uint32_t*)&h01, *(uint32_t*)&h23);
        *(uint2*)(sAl + row * 40 + aC4 * 4) =
            make_uint2(*(uint32_t*)&l01, *(uint32_t*)&l23);
    }
}

// ---------------------------------------------------------------------------
// Warp-MMA split-bf16 GEMM, 128x128 block tile, K=256 in 8 chunks of 32.
// Grid: x = N-tile (fast-varying -> L2 reuse of A), y = row-tile.
// Pipeline per iter: STS A ; wait B ; bar ; issue B(kc+1)+LDG A(kc+1) ; MMA.
// B fragments loaded PAIRWISE via ldmatrix.x4 (lanes 16-31 address the +8-row
// group), halving B LDSM issue count (16 x2 -> 8 x4 per s-step).
// 3 products per (mi,ni,k16): Ah*Bh + Ah*Bl + Al*Bh  (fp32 accumulate).
// EDGE=0: writes Q/K/V.  EDGE=1: per-edge head-score epilogue -> g_S.
// ---------------------------------------------------------------------------
template<int EDGE>
__global__ void __launch_bounds__(256, 2) mma_gemm_kernel(const float* __restrict__ Asrc) {
    extern __shared__ __align__(16) char dsm[];
    __shared__ int Ssrc[128], Sdst[128];

    const int tid  = threadIdx.x;
    const int wid  = tid >> 5;
    const int lane = tid & 31;
    const int wm   = wid & 3;
    const int wn   = wid >> 2;
    const int quad = lane & 3;
    const int qrow = lane >> 2;

    const int row0  = blockIdx.y * 128;
    const int nbase = blockIdx.x * 128;
    const int Mtot  = EDGE ? NE : NN;

    if (EDGE && tid < 128) {
        int ge = row0 + tid;
        if (ge > NE - 1) ge = NE - 1;
        Ssrc[tid] = g_src[ge];
        Sdst[tid] = g_dst[ge];
    }

    const float4* A4 = (const float4*)Asrc;
    const uint4* Bh4 = EDGE ? (const uint4*)g_WEh : (const uint4*)g_Wh;
    const uint4* Bl4 = EDGE ? (const uint4*)g_WEl : (const uint4*)g_Wl;

    float acc[2][8][4] = {};

    const uint32_t base = smem_u32(dsm);
    const uint32_t aOff = (uint32_t)((wm * 32 + (lane & 15)) * 80 + (lane >> 4) * 16);
    // x4 B layout: lanes 0-7 -> rows n..n+7 (k-half 0), 8-15 -> same rows
    // (k-half 1), 16-23 -> rows n+8..n+15 (k-half 0), 24-31 -> (k-half 1).
    const uint32_t bOffX4 = (uint32_t)((wn * 64 + (lane & 7) + (lane >> 4) * 8) * 80 +
                                       ((lane >> 3) & 1) * 16);

    // Per-thread fixed staging coords.
    const int aRow[4] = { (tid + 0) >> 3, (tid + 256) >> 3, (tid + 512) >> 3, (tid + 768) >> 3 };
    const int aC4 = tid & 7;
    long aRowG[4];
    #pragma unroll
    for (int l = 0; l < 4; ++l) aRowG[l] = min(row0 + aRow[l], Mtot - 1);

    // ---- prologue: prefetch A(0) regs; issue cp.async B(0) -> stage 0 ----
    float4 aPre[4];
    #pragma unroll
    for (int l = 0; l < 4; ++l) aPre[l] = A4[aRowG[l] * 64 + 0 + aC4];
    {
        uint32_t bB = base + B_BASE;   // stage 0
        #pragma unroll
        for (int l = 0; l < 4; ++l) {
            int idx = tid + l * 256;
            int sel = idx >> 9;
            int w   = idx & 511;
            int row = w >> 2;
            int c4  = w & 3;
            const uint4* gsrc = (sel ? Bl4 : Bh4) + (long)(nbase + row) * 32 + 0 + c4;
            cp_async16(bB + (uint32_t)(sel * HALF_BYTES + row * 80 + c4 * 16), gsrc);
        }
        cp_commit();
    }

    for (int kc = 0; kc < 8; ++kc) {
        const int st = kc & 1;
        const uint32_t aBase = base + st * STAGE_BYTES;
        const uint32_t bBase = base + B_BASE + st * STAGE_BYTES;

        // STS A(kc) into stage st (readers of this stage finished at sync(kc-1)).
        stsA(dsm + st * STAGE_BYTES, aPre, aRow, aC4);

        cp_wait0();        // B(kc) landed (issued a full iteration ago)
        __syncthreads();   // all warps done with MMA(kc-1); stages coherent

        // Issue B(kc+1) into the other stage; prefetch A(kc+1) regs.
        if (kc < 7) {
            uint32_t bBn = base + B_BASE + (st ^ 1) * STAGE_BYTES;
            #pragma unroll
            for (int l = 0; l < 4; ++l) {
                int idx = tid + l * 256;
                int sel = idx >> 9;
                int w   = idx & 511;
                int row = w >> 2;
                int c4  = w & 3;
                const uint4* gsrc = (sel ? Bl4 : Bh4) + (long)(nbase + row) * 32 + (kc + 1) * 4 + c4;
                cp_async16(bBn + (uint32_t)(sel * HALF_BYTES + row * 80 + c4 * 16), gsrc);
            }
            cp_commit();
            #pragma unroll
            for (int l = 0; l < 4; ++l)
                aPre[l] = A4[aRowG[l] * 64 + (kc + 1) * 8 + aC4];
        }

        // ---- MMA on stage st: B loaded pairwise via x4, interleaved accs ----
        #pragma unroll
        for (int s = 0; s < 2; ++s) {
            uint32_t ah[2][4], al[2][4];
            #pragma unroll
            for (int mi = 0; mi < 2; ++mi) {
                uint32_t o = aOff + (uint32_t)(mi * 16 * 80 + s * 32);
                ldsm_x4(ah[mi], aBase + o);
                ldsm_x4(al[mi], aBase + HALF_BYTES + o);
            }
            #pragma unroll
            for (int nj = 0; nj < 4; ++nj) {
                const int ni = nj * 2;
                uint32_t bo = bOffX4 + (uint32_t)(nj * 16 * 80 + s * 32);
                uint32_t bh[4], bl[4];           // [0:2)=ni, [2:4)=ni+1
                ldsm_x4(bh, bBase + bo);
                ldsm_x4(bl, bBase + HALF_BYTES + bo);
                // 12 MMAs; same-acc reuse distance = 4 issue slots.
                mma_bf16(acc[0][ni],     ah[0], bh + 0);
                mma_bf16(acc[0][ni + 1], ah[0], bh + 2);
                mma_bf16(acc[1][ni],     ah[1], bh + 0);
                mma_bf16(acc[1][ni + 1], ah[1], bh + 2);
                mma_bf16(acc[0][ni],     ah[0], bl + 0);
                mma_bf16(acc[0][ni + 1], ah[0], bl + 2);
                mma_bf16(acc[1][ni],     ah[1], bl + 0);
                mma_bf16(acc[1][ni + 1], ah[1], bl + 2);
                mma_bf16(acc[0][ni],     al[0], bh + 0);
                mma_bf16(acc[0][ni + 1], al[0], bh + 2);
                mma_bf16(acc[1][ni],     al[1], bh + 0);
                mma_bf16(acc[1][ni + 1], al[1], bh + 2);
            }
        }
    }

    if (EDGE) {
        // Per-edge head scores for this tile's 4 heads -> g_S.
        const float scale = 0.17677669529663687f;  // 1/sqrt(32)
        #pragma unroll
        for (int mi = 0; mi < 2; ++mi) {
            #pragma unroll
            for (int rh = 0; rh < 2; ++rh) {
                int r  = wm * 32 + mi * 16 + qrow + rh * 8;
                int ge = row0 + r;
                const float* Kr = g_K + (long)Ssrc[r] * DIMC + nbase + wn * 64;
                const float* Qr = g_Q + (long)Sdst[r] * DIMC + nbase + wn * 64;
                #pragma unroll
                for (int h = 0; h < 2; ++h) {
                    float p = 0.0f;
                    #pragma unroll
                    for (int j = 0; j < 4; ++j) {
                        int ni = h * 4 + j;
                        int c  = ni * 8 + quad * 2;
                        float2 kv = *(const float2*)(Kr + c);
                        float2 qv = *(const float2*)(Qr + c);
                        p += acc[mi][ni][rh * 2 + 0] * kv.x * qv.x;
                        p += acc[mi][ni][rh * 2 + 1] * kv.y * qv.y;
                    }
                    p += __shfl_xor_sync(0xffffffffu, p, 1);
                    p += __shfl_xor_sync(0xffffffffu, p, 2);
                    if (quad == 0 && ge < NE) {
                        float sv = fminf(5.0f, fmaxf(-5.0f, p * scale));
                        g_S[(long)ge * NH + (nbase >> 5) + wn * 2 + h] = expf(sv);
                    }
                }
            }
        }
    } else {
        int bx = blockIdx.x;
        float* Cout = (bx < 2) ? g_Q : (bx < 4) ? g_K : g_V;
        int colb = (bx & 1) * 128;
        #pragma unroll
        for (int mi = 0; mi < 2; ++mi) {
            #pragma unroll
            for (int ni = 0; ni < 8; ++ni) {
                int r = row0 + wm * 32 + mi * 16 + qrow;
                int c = colb + wn * 64 + ni * 8 + quad * 2;
                if (r < NN)
                    *(float2*)(Cout + (long)r * DIMC + c) =
                        make_float2(acc[mi][ni][0], acc[mi][ni][1]);
                if (r + 8 < NN)
                    *(float2*)(Cout + (long)(r + 8) * DIMC + c) =
                        make_float2(acc[mi][ni][2], acc[mi][ni][3]);
            }
        }
    }
}

// ---------------------------------------------------------------------------
// Scatter: wV[dst] += V[src]*score ; Z[dst,h] += score.  32 edges per block.
// Vectorized red.global.add.v4.f32: thread t covers column group (t&63)*4,
// edges (t>>6)*8 .. +7.  For fixed i, threads 0..63 sweep a full V row
// (64 float4 = 1KB, coalesced).  Z: 2 v4 reds per edge.
// ---------------------------------------------------------------------------
__global__ void scatter_kernel() {
    __shared__ int ssrc[32], sdst[32];
    __shared__ __align__(16) float ssc[32][NH];
    int e0 = blockIdx.x * 32;
    int tid = threadIdx.x;
    if (tid < 32) {
        int ge = e0 + tid;
        ssrc[tid] = (ge < NE) ? g_src[ge] : 0;
        sdst[tid] = (ge < NE) ? g_dst[ge] : 0;
    }
    {
        int el = tid >> 3, h = tid & 7;
        int ge = e0 + el;
        ssc[el][h] = (ge < NE) ? g_S[(long)ge * NH + h] : 0.0f;
    }
    __syncthreads();
    int cg = (tid & 63) * 4;        // column 0..252 step 4
    int h  = cg >> 5;               // head of this column group
    int ebeg = (tid >> 6) * 8;      // 4 edge groups of 8
    #pragma unroll
    for (int i = 0; i < 8; ++i) {
        int el = ebeg + i;
        int ge = e0 + el;
        if (ge < NE) {
            float s = ssc[el][h];
            float4 v = *(const float4*)(g_V + (long)ssrc[el] * DIMC + cg);
            v.x *= s; v.y *= s; v.z *= s; v.w *= s;
            red_v4(g_wV + (long)sdst[el] * DIMC + cg, v);
        }
    }
    if (tid < 64) {
        int el = tid >> 1, half = tid & 1;
        int ge = e0 + el;
        if (ge < NE) {
            float4 z = *(const float4*)(&ssc[el][half * 4]);
            red_v4(g_Z + (long)sdst[el] * NH + half * 4, z);
        }
    }
}

// ---------------------------------------------------------------------------
// Residual + BN column stats, then normalize.
// ---------------------------------------------------------------------------
__global__ void resid_stats_kernel(const float* __restrict__ x, float* __restrict__ out) {
    int c = threadIdx.x;
    int r0 = blockIdx.x * 256;
    int rend = min(NN, r0 + 256);
    float s = 0.0f, s2 = 0.0f;
    for (int n = r0; n < rend; ++n) {
        float z = g_Z[(long)n * NH + (c >> 5)] + 1e-6f;
        float h = x[(long)n * DIMC + c] + g_wV[(long)n * DIMC + c] / z;
        out[(long)n * DIMC + c] = h;
        s += h;
        s2 += h * h;
    }
    atomicAdd(&g_cs[c], s);
    atomicAdd(&g_cs2[c], s2);
}

__global__ void bn_norm_kernel(float* __restrict__ out,
                               const float* __restrict__ gamma,
                               const float* __restrict__ beta) {
    long total = (long)NN * DIMC;
    long stride = (long)gridDim.x * blockDim.x;
    const float invN = 1.0f / (float)NN;
    for (long i = (long)blockIdx.x * blockDim.x + threadIdx.x; i < total; i += stride) {
        int c = (int)(i & (DIMC - 1));
        float mean = g_cs[c] * invN;
        float var = g_cs2[c] * invN - mean * mean;
        out[i] = (out[i] - mean) * rsqrtf(var + 1e-5f) * gamma[c] + beta[c];
    }
}

extern "C" void kernel_launch(void* const* d_in, const int* in_sizes, int n_in,
                              void* d_out, int out_size) {
    const float* x     = (const float*)d_in[0];
    const float* ea    = (const float*)d_in[1];
    const float* WQ    = (const float*)d_in[2];
    const float* WK    = (const float*)d_in[3];
    const float* WE    = (const float*)d_in[4];
    const float* WV    = (const float*)d_in[5];
    const float* gamma = (const float*)d_in[6];
    const float* beta  = (const float*)d_in[7];
    const long long* eidx = (const long long*)d_in[8];
    float* out = (float*)d_out;

    // Opt-in to >48KB dynamic smem (attribute set, not an allocation).
    cudaFuncSetAttribute(mma_gemm_kernel<0>,
                         cudaFuncAttributeMaxDynamicSharedMemorySize, DYN_SMEM);
    cudaFuncSetAttribute(mma_gemm_kernel<1>,
                         cudaFuncAttributeMaxDynamicSharedMemorySize, DYN_SMEM);

    zero_kernel<<<1024, 256>>>();
    cvt_idx_kernel<<<512, 256>>>(eidx);
    prep_w_kernel<<<1024, 256>>>(WQ, WK, WV, WE);

    // QKV: x = N-tile (6), y = row-tile (782) -> schedule-adjacent CTAs share A.
    mma_gemm_kernel<0><<<dim3(6, 782), 256, DYN_SMEM>>>(x);
    // Edge: x = N-tile (2), y = row-tile (3907).
    mma_gemm_kernel<1><<<dim3(2, 3907), 256, DYN_SMEM>>>(ea);

    scatter_kernel<<<(NE + 31) / 32, 256>>>();
    resid_stats_kernel<<<(NN + 255) / 256, 256>>>(x, out);
    bn_norm_kernel<<<2048, 256>>>(out, gamma, beta);
}

// round 11
// speedup vs baseline: 1.4278x; 1.2159x over previous
#include <cuda_runtime.h>
#include <cuda_fp16.h>
#include <math.h>
#include <stdint.h>

#define NN 100000
#define NE 500000
#define DIMC 256
#define NH 8

// Dynamic smem layout (bytes):
//   A stage s (s=0,1): base + s*20480   -> Ah at +0, Al at +10240
//   B stage s:         base + 40960 + s*10240  (single fp16 copy of W)
#define A_STAGE_BYTES 20480
#define HALF_BYTES    10240
#define B_BASE        40960
#define B_STAGE_BYTES 10240
#define DYN_SMEM      61440

// ---------------------------------------------------------------------------
// Device-global scratch (no allocation allowed in kernel_launch)
// ---------------------------------------------------------------------------
__device__ float g_Q[NN * DIMC];
__device__ float g_K[NN * DIMC];
__device__ float g_V[NN * DIMC];
__device__ float g_wV[NN * DIMC];
__device__ float g_Z[NN * NH];
__device__ float g_S[NE * NH];
__device__ float g_cs[DIMC];
__device__ float g_cs2[DIMC];
__device__ int g_src[NE];
__device__ int g_dst[NE];
__device__ __half g_W[768 * DIMC];    // [n][k], QKV concat, fp16 RN
__device__ __half g_WE[DIMC * DIMC];  // [n][k], fp16 RN

// ---------------------------------------------------------------------------
// Warp-MMA helpers (portable PTX: ldmatrix + mma.sync + cp.async, sm_80+)
// ---------------------------------------------------------------------------
__device__ __forceinline__ uint32_t smem_u32(const void* p) {
    uint32_t a;
    asm("{ .reg .u64 t; cvta.to.shared.u64 t, %1; cvt.u32.u64 %0, t; }"
        : "=r"(a) : "l"(p));
    return a;
}
__device__ __forceinline__ void ldsm_x4(uint32_t* r, uint32_t addr) {
    asm volatile("ldmatrix.sync.aligned.m8n8.x4.shared.b16 {%0,%1,%2,%3}, [%4];"
                 : "=r"(r[0]), "=r"(r[1]), "=r"(r[2]), "=r"(r[3]) : "r"(addr));
}
__device__ __forceinline__ void mma_f16(float* d, const uint32_t* a, const uint32_t* b) {
    asm volatile(
        "mma.sync.aligned.m16n8k16.row.col.f32.f16.f16.f32 "
        "{%0,%1,%2,%3}, {%4,%5,%6,%7}, {%8,%9}, {%0,%1,%2,%3};"
        : "+f"(d[0]), "+f"(d[1]), "+f"(d[2]), "+f"(d[3])
        : "r"(a[0]), "r"(a[1]), "r"(a[2]), "r"(a[3]), "r"(b[0]), "r"(b[1]));
}
__device__ __forceinline__ void cp_async16(uint32_t saddr, const void* gptr) {
    asm volatile("cp.async.cg.shared.global [%0], [%1], 16;"
                 :: "r"(saddr), "l"(gptr) : "memory");
}
__device__ __forceinline__ void cp_commit() {
    asm volatile("cp.async.commit_group;" ::: "memory");
}
__device__ __forceinline__ void cp_wait0() {
    asm volatile("cp.async.wait_group 0;" ::: "memory");
}
// Vectorized global fp32 reduction (sm_90+): 4 adds in one instruction.
__device__ __forceinline__ void red_v4(float* gptr, float4 v) {
    asm volatile("red.global.add.v4.f32 [%0], {%1, %2, %3, %4};"
                 :: "l"(gptr), "f"(v.x), "f"(v.y), "f"(v.z), "f"(v.w) : "memory");
}

// ---------------------------------------------------------------------------
// Zero atomically-updated accumulators.
// ---------------------------------------------------------------------------
__global__ void zero_kernel() {
    long total = (long)NN * DIMC + (long)NN * NH;
    long stride = (long)gridDim.x * blockDim.x;
    for (long i = (long)blockIdx.x * blockDim.x + threadIdx.x; i < total; i += stride) {
        if (i < (long)NN * DIMC) g_wV[i] = 0.0f;
        else                     g_Z[i - (long)NN * DIMC] = 0.0f;
    }
    if (blockIdx.x == 0 && threadIdx.x < DIMC) {
        g_cs[threadIdx.x]  = 0.0f;
        g_cs2[threadIdx.x] = 0.0f;
    }
}

// ---------------------------------------------------------------------------
// edge_index -> int32 src/dst (handles int64 or int32 payload, deterministic)
// ---------------------------------------------------------------------------
__global__ void cvt_idx_kernel(const long long* __restrict__ e64) {
    const int* e32 = (const int*)e64;
    bool is64 = true;
    #pragma unroll
    for (int i = 0; i < 64; ++i)
        if ((e64[i] >> 32) != 0) is64 = false;
    long stride = (long)gridDim.x * blockDim.x;
    for (long e = (long)blockIdx.x * blockDim.x + threadIdx.x; e < NE; e += stride) {
        if (is64) { g_src[e] = (int)e64[e]; g_dst[e] = (int)e64[NE + e]; }
        else      { g_src[e] = e32[e];      g_dst[e] = e32[NE + e];      }
    }
}

// ---------------------------------------------------------------------------
// Weights transposed into B-operand layout [n][k], fp16 round-to-nearest.
// ---------------------------------------------------------------------------
__global__ void prep_w_kernel(const float* __restrict__ WQ, const float* __restrict__ WK,
                              const float* __restrict__ WV, const float* __restrict__ WE) {
    int i = blockIdx.x * 256 + threadIdx.x;   // 0 .. 1024*256-1
    if (i < 768 * DIMC) {
        int n = i >> 8;
        int k = i & 255;
        int m = n >> 8, nn = n & 255;
        const float* W = (m == 0) ? WQ : (m == 1) ? WK : WV;
        g_W[i] = __float2half_rn(W[k * DIMC + nn]);
    } else {
        int j = i - 768 * DIMC;
        int n = j >> 8, k = j & 255;
        g_WE[j] = __float2half_rn(WE[k * DIMC + n]);
    }
}

// ---------------------------------------------------------------------------
// Convert & store one A chunk (4 float4 per thread) to hi/lo fp16 smem stage.
// A = Ah + Al exactly to 2^-24; W single fp16 -> 2-pass MMA.
// ---------------------------------------------------------------------------
__device__ __forceinline__ void stsA(char* stage, const float4* v4,
                                     const int* aRow, int aC4) {
    __half* sAh = (__half*)stage;
    __half* sAl = (__half*)(stage + HALF_BYTES);
    #pragma unroll
    for (int l = 0; l < 4; ++l) {
        float4 v = v4[l];
        __half2 h01 = __floats2half2_rn(v.x, v.y);
        __half2 h23 = __floats2half2_rn(v.z, v.w);
        __half2 l01 = __floats2half2_rn(v.x - __half2float(__low2half(h01)),
                                        v.y - __half2float(__high2half(h01)));
        __half2 l23 = __floats2half2_rn(v.z - __half2float(__low2half(h23)),
                                        v.w - __half2float(__high2half(h23)));
        int row = aRow[l];
        *(uint2*)(sAh + row * 40 + aC4 * 4) =
            make_uint2(*(uint32_t*)&h01, *(uint32_t*)&h23);
        *(uint2*)(sAl + row * 40 + aC4 * 4) =
            make_uint2(*(uint32_t*)&l01, *(uint32_t*)&l23);
    }
}

// ---------------------------------------------------------------------------
// Warp-MMA split-fp16 GEMM, 128x128 block tile, K=256 in 8 chunks of 32.
// Grid: x = N-tile (fast-varying -> L2 reuse of A), y = row-tile.
// Pipeline per iter: STS A ; wait B ; bar ; issue B(kc+1)+LDG A(kc+1) ; MMA.
// 2 products per (mi,ni,k16): Ah*W + Al*W  (fp32 accumulate; W fp16-RN).
// B fragments loaded pairwise via ldmatrix.x4.
// EDGE=0: writes Q/K/V.  EDGE=1: per-edge head-score epilogue -> g_S.
// ---------------------------------------------------------------------------
template<int EDGE>
__global__ void __launch_bounds__(256, 2) mma_gemm_kernel(const float* __restrict__ Asrc) {
    extern __shared__ __align__(16) char dsm[];
    __shared__ int Ssrc[128], Sdst[128];

    const int tid  = threadIdx.x;
    const int wid  = tid >> 5;
    const int lane = tid & 31;
    const int wm   = wid & 3;
    const int wn   = wid >> 2;
    const int quad = lane & 3;
    const int qrow = lane >> 2;

    const int row0  = blockIdx.y * 128;
    const int nbase = blockIdx.x * 128;
    const int Mtot  = EDGE ? NE : NN;

    if (EDGE && tid < 128) {
        int ge = row0 + tid;
        if (ge > NE - 1) ge = NE - 1;
        Ssrc[tid] = g_src[ge];
        Sdst[tid] = g_dst[ge];
    }

    const float4* A4 = (const float4*)Asrc;
    const uint4* B4 = EDGE ? (const uint4*)g_WE : (const uint4*)g_W;

    float acc[2][8][4] = {};

    const uint32_t base = smem_u32(dsm);
    const uint32_t aOff = (uint32_t)((wm * 32 + (lane & 15)) * 80 + (lane >> 4) * 16);
    // x4 B layout: lanes 0-7 -> rows n..n+7 (k-half 0), 8-15 -> same rows
    // (k-half 1), 16-23 -> rows n+8..n+15 (k-half 0), 24-31 -> (k-half 1).
    const uint32_t bOffX4 = (uint32_t)((wn * 64 + (lane & 7) + (lane >> 4) * 8) * 80 +
                                       ((lane >> 3) & 1) * 16);

    // Per-thread fixed staging coords.
    const int aRow[4] = { (tid + 0) >> 3, (tid + 256) >> 3, (tid + 512) >> 3, (tid + 768) >> 3 };
    const int aC4 = tid & 7;
    long aRowG[4];
    #pragma unroll
    for (int l = 0; l < 4; ++l) aRowG[l] = min(row0 + aRow[l], Mtot - 1);
    // B staging: 128 rows x 32 fp16 = 512 x 16B; 2 per thread.
    const int bRow[2] = { (tid + 0) >> 2, (tid + 256) >> 2 };
    const int bC4 = tid & 3;

    // ---- prologue: prefetch A(0) regs; issue cp.async B(0) -> stage 0 ----
    float4 aPre[4];
    #pragma unroll
    for (int l = 0; l < 4; ++l) aPre[l] = A4[aRowG[l] * 64 + 0 + aC4];
    {
        uint32_t bB = base + B_BASE;   // stage 0
        #pragma unroll
        for (int l = 0; l < 2; ++l) {
            const uint4* gsrc = B4 + (long)(nbase + bRow[l]) * 32 + 0 + bC4;
            cp_async16(bB + (uint32_t)(bRow[l] * 80 + bC4 * 16), gsrc);
        }
        cp_commit();
    }

    for (int kc = 0; kc < 8; ++kc) {
        const int st = kc & 1;
        const uint32_t aBase = base + st * A_STAGE_BYTES;
        const uint32_t bBase = base + B_BASE + st * B_STAGE_BYTES;

        // STS A(kc) into stage st (readers of this stage finished at sync(kc-1)).
        stsA(dsm + st * A_STAGE_BYTES, aPre, aRow, aC4);

        cp_wait0();        // B(kc) landed (issued a full iteration ago)
        __syncthreads();   // all warps done with MMA(kc-1); stages coherent

        // Issue B(kc+1) into the other stage; prefetch A(kc+1) regs.
        if (kc < 7) {
            uint32_t bBn = base + B_BASE + (st ^ 1) * B_STAGE_BYTES;
            #pragma unroll
            for (int l = 0; l < 2; ++l) {
                const uint4* gsrc = B4 + (long)(nbase + bRow[l]) * 32 + (kc + 1) * 4 + bC4;
                cp_async16(bBn + (uint32_t)(bRow[l] * 80 + bC4 * 16), gsrc);
            }
            cp_commit();
            #pragma unroll
            for (int l = 0; l < 4; ++l)
                aPre[l] = A4[aRowG[l] * 64 + (kc + 1) * 8 + aC4];
        }

        // ---- MMA on stage st: 2-pass fp16, interleaved accumulators ----
        #pragma unroll
        for (int s = 0; s < 2; ++s) {
            uint32_t ah[2][4], al[2][4];
            #pragma unroll
            for (int mi = 0; mi < 2; ++mi) {
                uint32_t o = aOff + (uint32_t)(mi * 16 * 80 + s * 32);
                ldsm_x4(ah[mi], aBase + o);
                ldsm_x4(al[mi], aBase + HALF_BYTES + o);
            }
            #pragma unroll
            for (int nj = 0; nj < 4; ++nj) {
                const int ni = nj * 2;
                uint32_t bo = bOffX4 + (uint32_t)(nj * 16 * 80 + s * 32);
                uint32_t bf[4];                  // [0:2)=ni, [2:4)=ni+1
                ldsm_x4(bf, bBase + bo);
                // 8 MMAs; same-acc reuse distance = 4 issue slots.
                mma_f16(acc[0][ni],     ah[0], bf + 0);
                mma_f16(acc[0][ni + 1], ah[0], bf + 2);
                mma_f16(acc[1][ni],     ah[1], bf + 0);
                mma_f16(acc[1][ni + 1], ah[1], bf + 2);
                mma_f16(acc[0][ni],     al[0], bf + 0);
                mma_f16(acc[0][ni + 1], al[0], bf + 2);
                mma_f16(acc[1][ni],     al[1], bf + 0);
                mma_f16(acc[1][ni + 1], al[1], bf + 2);
            }
        }
    }

    if (EDGE) {
        // Per-edge head scores for this tile's 4 heads -> g_S.
        const float scale = 0.17677669529663687f;  // 1/sqrt(32)
        #pragma unroll
        for (int mi = 0; mi < 2; ++mi) {
            #pragma unroll
            for (int rh = 0; rh < 2; ++rh) {
                int r  = wm * 32 + mi * 16 + qrow + rh * 8;
                int ge = row0 + r;
                const float* Kr = g_K + (long)Ssrc[r] * DIMC + nbase + wn * 64;
                const float* Qr = g_Q + (long)Sdst[r] * DIMC + nbase + wn * 64;
                #pragma unroll
                for (int h = 0; h < 2; ++h) {
                    float p = 0.0f;
                    #pragma unroll
                    for (int j = 0; j < 4; ++j) {
                        int ni = h * 4 + j;
                        int c  = ni * 8 + quad * 2;
                        float2 kv = *(const float2*)(Kr + c);
                        float2 qv = *(const float2*)(Qr + c);
                        p += acc[mi][ni][rh * 2 + 0] * kv.x * qv.x;
                        p += acc[mi][ni][rh * 2 + 1] * kv.y * qv.y;
                    }
                    p += __shfl_xor_sync(0xffffffffu, p, 1);
                    p += __shfl_xor_sync(0xffffffffu, p, 2);
                    if (quad == 0 && ge < NE) {
                        float sv = fminf(5.0f, fmaxf(-5.0f, p * scale));
                        g_S[(long)ge * NH + (nbase >> 5) + wn * 2 + h] = expf(sv);
                    }
                }
            }
        }
    } else {
        int bx = blockIdx.x;
        float* Cout = (bx < 2) ? g_Q : (bx < 4) ? g_K : g_V;
        int colb = (bx & 1) * 128;
        #pragma unroll
        for (int mi = 0; mi < 2; ++mi) {
            #pragma unroll
            for (int ni = 0; ni < 8; ++ni) {
                int r = row0 + wm * 32 + mi * 16 + qrow;
                int c = colb + wn * 64 + ni * 8 + quad * 2;
                if (r < NN)
                    *(float2*)(Cout + (long)r * DIMC + c) =
                        make_float2(acc[mi][ni][0], acc[mi][ni][1]);
                if (r + 8 < NN)
                    *(float2*)(Cout + (long)(r + 8) * DIMC + c) =
                        make_float2(acc[mi][ni][2], acc[mi][ni][3]);
            }
        }
    }
}

// ---------------------------------------------------------------------------
// Scatter: wV[dst] += V[src]*score ; Z[dst,h] += score.  32 edges per block.
// Vectorized red.global.add.v4.f32: thread t covers column group (t&63)*4,
// edges (t>>6)*8 .. +7.
// ---------------------------------------------------------------------------
__global__ void scatter_kernel() {
    __shared__ int ssrc[32], sdst[32];
    __shared__ __align__(16) float ssc[32][NH];
    int e0 = blockIdx.x * 32;
    int tid = threadIdx.x;
    if (tid < 32) {
        int ge = e0 + tid;
        ssrc[tid] = (ge < NE) ? g_src[ge] : 0;
        sdst[tid] = (ge < NE) ? g_dst[ge] : 0;
    }
    {
        int el = tid >> 3, h = tid & 7;
        int ge = e0 + el;
        ssc[el][h] = (ge < NE) ? g_S[(long)ge * NH + h] : 0.0f;
    }
    __syncthreads();
    int cg = (tid & 63) * 4;        // column 0..252 step 4
    int h  = cg >> 5;               // head of this column group
    int ebeg = (tid >> 6) * 8;      // 4 edge groups of 8
    #pragma unroll
    for (int i = 0; i < 8; ++i) {
        int el = ebeg + i;
        int ge = e0 + el;
        if (ge < NE) {
            float s = ssc[el][h];
            float4 v = *(const float4*)(g_V + (long)ssrc[el] * DIMC + cg);
            v.x *= s; v.y *= s; v.z *= s; v.w *= s;
            red_v4(g_wV + (long)sdst[el] * DIMC + cg, v);
        }
    }
    if (tid < 64) {
        int el = tid >> 1, half = tid & 1;
        int ge = e0 + el;
        if (ge < NE) {
            float4 z = *(const float4*)(&ssc[el][half * 4]);
            red_v4(g_Z + (long)sdst[el] * NH + half * 4, z);
        }
    }
}

// ---------------------------------------------------------------------------
// Residual + BN column stats, then normalize.
// ---------------------------------------------------------------------------
__global__ void resid_stats_kernel(const float* __restrict__ x, float* __restrict__ out) {
    int c = threadIdx.x;
    int r0 = blockIdx.x * 256;
    int rend = min(NN, r0 + 256);
    float s = 0.0f, s2 = 0.0f;
    for (int n = r0; n < rend; ++n) {
        float z = g_Z[(long)n * NH + (c >> 5)] + 1e-6f;
        float h = x[(long)n * DIMC + c] + g_wV[(long)n * DIMC + c] / z;
        out[(long)n * DIMC + c] = h;
        s += h;
        s2 += h * h;
    }
    atomicAdd(&g_cs[c], s);
    atomicAdd(&g_cs2[c], s2);
}

__global__ void bn_norm_kernel(float* __restrict__ out,
                               const float* __restrict__ gamma,
                               const float* __restrict__ beta) {
    long total = (long)NN * DIMC;
    long stride = (long)gridDim.x * blockDim.x;
    const float invN = 1.0f / (float)NN;
    for (long i = (long)blockIdx.x * blockDim.x + threadIdx.x; i < total; i += stride) {
        int c = (int)(i & (DIMC - 1));
        float mean = g_cs[c] * invN;
        float var = g_cs2[c] * invN - mean * mean;
        out[i] = (out[i] - mean) * rsqrtf(var + 1e-5f) * gamma[c] + beta[c];
    }
}

extern "C" void kernel_launch(void* const* d_in, const int* in_sizes, int n_in,
                              void* d_out, int out_size) {
    const float* x     = (const float*)d_in[0];
    const float* ea    = (const float*)d_in[1];
    const float* WQ    = (const float*)d_in[2];
    const float* WK    = (const float*)d_in[3];
    const float* WE    = (const float*)d_in[4];
    const float* WV    = (const float*)d_in[5];
    const float* gamma = (const float*)d_in[6];
    const float* beta  = (const float*)d_in[7];
    const long long* eidx = (const long long*)d_in[8];
    float* out = (float*)d_out;

    // Opt-in to >48KB dynamic smem (attribute set, not an allocation).
    cudaFuncSetAttribute(mma_gemm_kernel<0>,
                         cudaFuncAttributeMaxDynamicSharedMemorySize, DYN_SMEM);
    cudaFuncSetAttribute(mma_gemm_kernel<1>,
                         cudaFuncAttributeMaxDynamicSharedMemorySize, DYN_SMEM);

    zero_kernel<<<1024, 256>>>();
    cvt_idx_kernel<<<512, 256>>>(eidx);
    prep_w_kernel<<<1024, 256>>>(WQ, WK, WV, WE);

    // QKV: x = N-tile (6), y = row-tile (782) -> schedule-adjacent CTAs share A.
    mma_gemm_kernel<0><<<dim3(6, 782), 256, DYN_SMEM>>>(x);
    // Edge: x = N-tile (2), y = row-tile (3907).
    mma_gemm_kernel<1><<<dim3(2, 3907), 256, DYN_SMEM>>>(ea);

    scatter_kernel<<<(NE + 31) / 32, 256>>>();
    resid_stats_kernel<<<(NN + 255) / 256, 256>>>(x, out);
    bn_norm_kernel<<<2048, 256>>>(out, gamma, beta);
}

// round 12
// speedup vs baseline: 1.5721x; 1.1010x over previous
#include <cuda_runtime.h>
#include <cuda_fp16.h>
#include <math.h>
#include <stdint.h>

#define NN 100000
#define NE 500000
#define DIMC 256
#define NH 8

// Dynamic smem layout (bytes):
//   A stage s (s=0,1): base + s*10240          (single fp16 copy of A chunk)
//   B stage s:         base + 20480 + s*10240  (single fp16 copy of W chunk)
#define A_STAGE_BYTES 10240
#define B_BASE        20480
#define B_STAGE_BYTES 10240
#define DYN_SMEM      40960

// ---------------------------------------------------------------------------
// Device-global scratch (no allocation allowed in kernel_launch)
// ---------------------------------------------------------------------------
__device__ float g_Q[NN * DIMC];
__device__ float g_K[NN * DIMC];
__device__ float g_V[NN * DIMC];
__device__ float g_wV[NN * DIMC];
__device__ float g_Z[NN * NH];
__device__ float g_S[NE * NH];
__device__ float g_cs[DIMC];
__device__ float g_cs2[DIMC];
__device__ int g_src[NE];
__device__ int g_dst[NE];
__device__ __half g_W[768 * DIMC];    // [n][k], QKV concat, fp16 RN
__device__ __half g_WE[DIMC * DIMC];  // [n][k], fp16 RN

// ---------------------------------------------------------------------------
// Warp-MMA helpers (portable PTX: ldmatrix + mma.sync + cp.async, sm_80+)
// ---------------------------------------------------------------------------
__device__ __forceinline__ uint32_t smem_u32(const void* p) {
    uint32_t a;
    asm("{ .reg .u64 t; cvta.to.shared.u64 t, %1; cvt.u32.u64 %0, t; }"
        : "=r"(a) : "l"(p));
    return a;
}
__device__ __forceinline__ void ldsm_x4(uint32_t* r, uint32_t addr) {
    asm volatile("ldmatrix.sync.aligned.m8n8.x4.shared.b16 {%0,%1,%2,%3}, [%4];"
                 : "=r"(r[0]), "=r"(r[1]), "=r"(r[2]), "=r"(r[3]) : "r"(addr));
}
__device__ __forceinline__ void mma_f16(float* d, const uint32_t* a, const uint32_t* b) {
    asm volatile(
        "mma.sync.aligned.m16n8k16.row.col.f32.f16.f16.f32 "
        "{%0,%1,%2,%3}, {%4,%5,%6,%7}, {%8,%9}, {%0,%1,%2,%3};"
        : "+f"(d[0]), "+f"(d[1]), "+f"(d[2]), "+f"(d[3])
        : "r"(a[0]), "r"(a[1]), "r"(a[2]), "r"(a[3]), "r"(b[0]), "r"(b[1]));
}
__device__ __forceinline__ void cp_async16(uint32_t saddr, const void* gptr) {
    asm volatile("cp.async.cg.shared.global [%0], [%1], 16;"
                 :: "r"(saddr), "l"(gptr) : "memory");
}
__device__ __forceinline__ void cp_commit() {
    asm volatile("cp.async.commit_group;" ::: "memory");
}
__device__ __forceinline__ void cp_wait0() {
    asm volatile("cp.async.wait_group 0;" ::: "memory");
}
// Vectorized global fp32 reduction (sm_90+): 4 adds in one instruction.
__device__ __forceinline__ void red_v4(float* gptr, float4 v) {
    asm volatile("red.global.add.v4.f32 [%0], {%1, %2, %3, %4};"
                 :: "l"(gptr), "f"(v.x), "f"(v.y), "f"(v.z), "f"(v.w) : "memory");
}

// ---------------------------------------------------------------------------
// Zero atomically-updated accumulators.
// ---------------------------------------------------------------------------
__global__ void zero_kernel() {
    long total = (long)NN * DIMC + (long)NN * NH;
    long stride = (long)gridDim.x * blockDim.x;
    for (long i = (long)blockIdx.x * blockDim.x + threadIdx.x; i < total; i += stride) {
        if (i < (long)NN * DIMC) g_wV[i] = 0.0f;
        else                     g_Z[i - (long)NN * DIMC] = 0.0f;
    }
    if (blockIdx.x == 0 && threadIdx.x < DIMC) {
        g_cs[threadIdx.x]  = 0.0f;
        g_cs2[threadIdx.x] = 0.0f;
    }
}

// ---------------------------------------------------------------------------
// edge_index -> int32 src/dst (handles int64 or int32 payload, deterministic)
// ---------------------------------------------------------------------------
__global__ void cvt_idx_kernel(const long long* __restrict__ e64) {
    const int* e32 = (const int*)e64;
    bool is64 = true;
    #pragma unroll
    for (int i = 0; i < 64; ++i)
        if ((e64[i] >> 32) != 0) is64 = false;
    long stride = (long)gridDim.x * blockDim.x;
    for (long e = (long)blockIdx.x * blockDim.x + threadIdx.x; e < NE; e += stride) {
        if (is64) { g_src[e] = (int)e64[e]; g_dst[e] = (int)e64[NE + e]; }
        else      { g_src[e] = e32[e];      g_dst[e] = e32[NE + e];      }
    }
}

// ---------------------------------------------------------------------------
// Weights transposed into B-operand layout [n][k], fp16 round-to-nearest.
// ---------------------------------------------------------------------------
__global__ void prep_w_kernel(const float* __restrict__ WQ, const float* __restrict__ WK,
                              const float* __restrict__ WV, const float* __restrict__ WE) {
    int i = blockIdx.x * 256 + threadIdx.x;   // 0 .. 1024*256-1
    if (i < 768 * DIMC) {
        int n = i >> 8;
        int k = i & 255;
        int m = n >> 8, nn = n & 255;
        const float* W = (m == 0) ? WQ : (m == 1) ? WK : WV;
        g_W[i] = __float2half_rn(W[k * DIMC + nn]);
    } else {
        int j = i - 768 * DIMC;
        int n = j >> 8, k = j & 255;
        g_WE[j] = __float2half_rn(WE[k * DIMC + n]);
    }
}

// ---------------------------------------------------------------------------
// Convert & store one A chunk (4 float4 per thread) to fp16 smem stage.
// ---------------------------------------------------------------------------
__device__ __forceinline__ void stsA(char* stage, const float4* v4,
                                     const int* aRow, int aC4) {
    __half* sA = (__half*)stage;
    #pragma unroll
    for (int l = 0; l < 4; ++l) {
        float4 v = v4[l];
        __half2 h01 = __floats2half2_rn(v.x, v.y);
        __half2 h23 = __floats2half2_rn(v.z, v.w);
        int row = aRow[l];
        *(uint2*)(sA + row * 40 + aC4 * 4) =
            make_uint2(*(uint32_t*)&h01, *(uint32_t*)&h23);
    }
}

// ---------------------------------------------------------------------------
// Warp-MMA fp16 GEMM (1-pass), 128x128 block tile, K=256 in 8 chunks of 32.
// Grid: x = N-tile (fast-varying -> L2 reuse of A), y = row-tile.
// Pipeline per iter: STS A ; wait B ; bar ; issue B(kc+1)+LDG A(kc+1) ; MMA.
// B fragments loaded pairwise via ldmatrix.x4; accumulators interleaved.
// EDGE=0: writes Q/K/V.  EDGE=1: per-edge head-score epilogue -> g_S.
// ---------------------------------------------------------------------------
template<int EDGE>
__global__ void __launch_bounds__(256, 2) mma_gemm_kernel(const float* __restrict__ Asrc) {
    extern __shared__ __align__(16) char dsm[];
    __shared__ int Ssrc[128], Sdst[128];

    const int tid  = threadIdx.x;
    const int wid  = tid >> 5;
    const int lane = tid & 31;
    const int wm   = wid & 3;
    const int wn   = wid >> 2;
    const int quad = lane & 3;
    const int qrow = lane >> 2;

    const int row0  = blockIdx.y * 128;
    const int nbase = blockIdx.x * 128;
    const int Mtot  = EDGE ? NE : NN;

    if (EDGE && tid < 128) {
        int ge = row0 + tid;
        if (ge > NE - 1) ge = NE - 1;
        Ssrc[tid] = g_src[ge];
        Sdst[tid] = g_dst[ge];
    }

    const float4* A4 = (const float4*)Asrc;
    const uint4* B4 = EDGE ? (const uint4*)g_WE : (const uint4*)g_W;

    float acc[2][8][4] = {};

    const uint32_t base = smem_u32(dsm);
    const uint32_t aOff = (uint32_t)((wm * 32 + (lane & 15)) * 80 + (lane >> 4) * 16);
    // x4 B layout: lanes 0-7 -> rows n..n+7 (k-half 0), 8-15 -> same rows
    // (k-half 1), 16-23 -> rows n+8..n+15 (k-half 0), 24-31 -> (k-half 1).
    const uint32_t bOffX4 = (uint32_t)((wn * 64 + (lane & 7) + (lane >> 4) * 8) * 80 +
                                       ((lane >> 3) & 1) * 16);

    // Per-thread fixed staging coords.
    const int aRow[4] = { (tid + 0) >> 3, (tid + 256) >> 3, (tid + 512) >> 3, (tid + 768) >> 3 };
    const int aC4 = tid & 7;
    long aRowG[4];
    #pragma unroll
    for (int l = 0; l < 4; ++l) aRowG[l] = min(row0 + aRow[l], Mtot - 1);
    // B staging: 128 rows x 32 fp16 = 512 x 16B; 2 per thread.
    const int bRow[2] = { (tid + 0) >> 2, (tid + 256) >> 2 };
    const int bC4 = tid & 3;

    // ---- prologue: prefetch A(0) regs; issue cp.async B(0) -> stage 0 ----
    float4 aPre[4];
    #pragma unroll
    for (int l = 0; l < 4; ++l) aPre[l] = A4[aRowG[l] * 64 + 0 + aC4];
    {
        uint32_t bB = base + B_BASE;   // stage 0
        #pragma unroll
        for (int l = 0; l < 2; ++l) {
            const uint4* gsrc = B4 + (long)(nbase + bRow[l]) * 32 + 0 + bC4;
            cp_async16(bB + (uint32_t)(bRow[l] * 80 + bC4 * 16), gsrc);
        }
        cp_commit();
    }

    for (int kc = 0; kc < 8; ++kc) {
        const int st = kc & 1;
        const uint32_t aBase = base + st * A_STAGE_BYTES;
        const uint32_t bBase = base + B_BASE + st * B_STAGE_BYTES;

        // STS A(kc) into stage st (readers of this stage finished at sync(kc-1)).
        stsA(dsm + st * A_STAGE_BYTES, aPre, aRow, aC4);

        cp_wait0();        // B(kc) landed (issued a full iteration ago)
        __syncthreads();   // all warps done with MMA(kc-1); stages coherent

        // Issue B(kc+1) into the other stage; prefetch A(kc+1) regs.
        if (kc < 7) {
            uint32_t bBn = base + B_BASE + (st ^ 1) * B_STAGE_BYTES;
            #pragma unroll
            for (int l = 0; l < 2; ++l) {
                const uint4* gsrc = B4 + (long)(nbase + bRow[l]) * 32 + (kc + 1) * 4 + bC4;
                cp_async16(bBn + (uint32_t)(bRow[l] * 80 + bC4 * 16), gsrc);
            }
            cp_commit();
            #pragma unroll
            for (int l = 0; l < 4; ++l)
                aPre[l] = A4[aRowG[l] * 64 + (kc + 1) * 8 + aC4];
        }

        // ---- MMA on stage st: 1-pass fp16, interleaved accumulators ----
        #pragma unroll
        for (int s = 0; s < 2; ++s) {
            uint32_t ah[2][4];
            #pragma unroll
            for (int mi = 0; mi < 2; ++mi) {
                uint32_t o = aOff + (uint32_t)(mi * 16 * 80 + s * 32);
                ldsm_x4(ah[mi], aBase + o);
            }
            #pragma unroll
            for (int nj = 0; nj < 4; ++nj) {
                const int ni = nj * 2;
                uint32_t bo = bOffX4 + (uint32_t)(nj * 16 * 80 + s * 32);
                uint32_t bf[4];                  // [0:2)=ni, [2:4)=ni+1
                ldsm_x4(bf, bBase + bo);
                // 4 MMAs; same-acc reuse distance = 4 issue slots.
                mma_f16(acc[0][ni],     ah[0], bf + 0);
                mma_f16(acc[0][ni + 1], ah[0], bf + 2);
                mma_f16(acc[1][ni],     ah[1], bf + 0);
                mma_f16(acc[1][ni + 1], ah[1], bf + 2);
            }
        }
    }

    if (EDGE) {
        // Per-edge head scores for this tile's 4 heads -> g_S.
        const float scale = 0.17677669529663687f;  // 1/sqrt(32)
        #pragma unroll
        for (int mi = 0; mi < 2; ++mi) {
            #pragma unroll
            for (int rh = 0; rh < 2; ++rh) {
                int r  = wm * 32 + mi * 16 + qrow + rh * 8;
                int ge = row0 + r;
                const float* Kr = g_K + (long)Ssrc[r] * DIMC + nbase + wn * 64;
                const float* Qr = g_Q + (long)Sdst[r] * DIMC + nbase + wn * 64;
                #pragma unroll
                for (int h = 0; h < 2; ++h) {
                    float p = 0.0f;
                    #pragma unroll
                    for (int j = 0; j < 4; ++j) {
                        int ni = h * 4 + j;
                        int c  = ni * 8 + quad * 2;
                        float2 kv = *(const float2*)(Kr + c);
                        float2 qv = *(const float2*)(Qr + c);
                        p += acc[mi][ni][rh * 2 + 0] * kv.x * qv.x;
                        p += acc[mi][ni][rh * 2 + 1] * kv.y * qv.y;
                    }
                    p += __shfl_xor_sync(0xffffffffu, p, 1);
                    p += __shfl_xor_sync(0xffffffffu, p, 2);
                    if (quad == 0 && ge < NE) {
                        float sv = fminf(5.0f, fmaxf(-5.0f, p * scale));
                        g_S[(long)ge * NH + (nbase >> 5) + wn * 2 + h] = expf(sv);
                    }
                }
            }
        }
    } else {
        int bx = blockIdx.x;
        float* Cout = (bx < 2) ? g_Q : (bx < 4) ? g_K : g_V;
        int colb = (bx & 1) * 128;
        #pragma unroll
        for (int mi = 0; mi < 2; ++mi) {
            #pragma unroll
            for (int ni = 0; ni < 8; ++ni) {
                int r = row0 + wm * 32 + mi * 16 + qrow;
                int c = colb + wn * 64 + ni * 8 + quad * 2;
                if (r < NN)
                    *(float2*)(Cout + (long)r * DIMC + c) =
                        make_float2(acc[mi][ni][0], acc[mi][ni][1]);
                if (r + 8 < NN)
                    *(float2*)(Cout + (long)(r + 8) * DIMC + c) =
                        make_float2(acc[mi][ni][2], acc[mi][ni][3]);
            }
        }
    }
}

// ---------------------------------------------------------------------------
// Scatter: wV[dst] += V[src]*score ; Z[dst,h] += score.  32 edges per block.
// Vectorized red.global.add.v4.f32: thread t covers column group (t&63)*4,
// edges (t>>6)*8 .. +7.
// ---------------------------------------------------------------------------
__global__ void scatter_kernel() {
    __shared__ int ssrc[32], sdst[32];
    __shared__ __align__(16) float ssc[32][NH];
    int e0 = blockIdx.x * 32;
    int tid = threadIdx.x;
    if (tid < 32) {
        int ge = e0 + tid;
        ssrc[tid] = (ge < NE) ? g_src[ge] : 0;
        sdst[tid] = (ge < NE) ? g_dst[ge] : 0;
    }
    {
        int el = tid >> 3, h = tid & 7;
        int ge = e0 + el;
        ssc[el][h] = (ge < NE) ? g_S[(long)ge * NH + h] : 0.0f;
    }
    __syncthreads();
    int cg = (tid & 63) * 4;        // column 0..252 step 4
    int h  = cg >> 5;               // head of this column group
    int ebeg = (tid >> 6) * 8;      // 4 edge groups of 8
    #pragma unroll
    for (int i = 0; i < 8; ++i) {
        int el = ebeg + i;
        int ge = e0 + el;
        if (ge < NE) {
            float s = ssc[el][h];
            float4 v = *(const float4*)(g_V + (long)ssrc[el] * DIMC + cg);
            v.x *= s; v.y *= s; v.z *= s; v.w *= s;
            red_v4(g_wV + (long)sdst[el] * DIMC + cg, v);
        }
    }
    if (tid < 64) {
        int el = tid >> 1, half = tid & 1;
        int ge = e0 + el;
        if (ge < NE) {
            float4 z = *(const float4*)(&ssc[el][half * 4]);
            red_v4(g_Z + (long)sdst[el] * NH + half * 4, z);
        }
    }
}

// ---------------------------------------------------------------------------
// Residual + BN column stats, then normalize.
// ---------------------------------------------------------------------------
__global__ void resid_stats_kernel(const float* __restrict__ x, float* __restrict__ out) {
    int c = threadIdx.x;
    int r0 = blockIdx.x * 256;
    int rend = min(NN, r0 + 256);
    float s = 0.0f, s2 = 0.0f;
    for (int n = r0; n < rend; ++n) {
        float z = g_Z[(long)n * NH + (c >> 5)] + 1e-6f;
        float h = x[(long)n * DIMC + c] + g_wV[(long)n * DIMC + c] / z;
        out[(long)n * DIMC + c] = h;
        s += h;
        s2 += h * h;
    }
    atomicAdd(&g_cs[c], s);
    atomicAdd(&g_cs2[c], s2);
}

__global__ void bn_norm_kernel(float* __restrict__ out,
                               const float* __restrict__ gamma,
                               const float* __restrict__ beta) {
    long total = (long)NN * DIMC;
    long stride = (long)gridDim.x * blockDim.x;
    const float invN = 1.0f / (float)NN;
    for (long i = (long)blockIdx.x * blockDim.x + threadIdx.x; i < total; i += stride) {
        int c = (int)(i & (DIMC - 1));
        float mean = g_cs[c] * invN;
        float var = g_cs2[c] * invN - mean * mean;
        out[i] = (out[i] - mean) * rsqrtf(var + 1e-5f) * gamma[c] + beta[c];
    }
}

extern "C" void kernel_launch(void* const* d_in, const int* in_sizes, int n_in,
                              void* d_out, int out_size) {
    const float* x     = (const float*)d_in[0];
    const float* ea    = (const float*)d_in[1];
    const float* WQ    = (const float*)d_in[2];
    const float* WK    = (const float*)d_in[3];
    const float* WE    = (const float*)d_in[4];
    const float* WV    = (const float*)d_in[5];
    const float* gamma = (const float*)d_in[6];
    const float* beta  = (const float*)d_in[7];
    const long long* eidx = (const long long*)d_in[8];
    float* out = (float*)d_out;

    zero_kernel<<<1024, 256>>>();
    cvt_idx_kernel<<<512, 256>>>(eidx);
    prep_w_kernel<<<1024, 256>>>(WQ, WK, WV, WE);

    // QKV: x = N-tile (6), y = row-tile (782) -> schedule-adjacent CTAs share A.
    mma_gemm_kernel<0><<<dim3(6, 782), 256, DYN_SMEM>>>(x);
    // Edge: x = N-tile (2), y = row-tile (3907).
    mma_gemm_kernel<1><<<dim3(2, 3907), 256, DYN_SMEM>>>(ea);

    scatter_kernel<<<(NE + 31) / 32, 256>>>();
    resid_stats_kernel<<<(NN + 255) / 256, 256>>>(x, out);
    bn_norm_kernel<<<2048, 256>>>(out, gamma, beta);
}

// round 13
// speedup vs baseline: 1.6945x; 1.0778x over previous
#include <cuda_runtime.h>
#include <cuda_fp16.h>
#include <math.h>
#include <stdint.h>

#define NN 100000
#define NE 500000
#define DIMC 256
#define NH 8
#define NBLK 391   // ceil(NN/256)

// Dynamic smem layout (bytes):
//   A stage s (s=0,1): base + s*10240          (single fp16 copy of A chunk)
//   B stage s:         base + 20480 + s*10240  (single fp16 copy of W chunk)
#define A_STAGE_BYTES 10240
#define B_BASE        20480
#define B_STAGE_BYTES 10240
#define DYN_SMEM      40960

// ---------------------------------------------------------------------------
// Device-global scratch (no allocation allowed in kernel_launch)
// ---------------------------------------------------------------------------
__device__ float g_Q[NN * DIMC];
__device__ float g_K[NN * DIMC];
__device__ float g_V[NN * DIMC];
__device__ float g_S[NE * NH];
__device__ float g_cs[DIMC];
__device__ float g_cs2[DIMC];
__device__ int g_src[NE];
__device__ int g_dst[NE];
__device__ int g_cnt[NN];        // per-dst degree histogram
__device__ int g_off[NN + 1];    // CSR offsets (exclusive scan of cnt)
__device__ int g_cur[NN];        // running cursor for build pass
__device__ int g_blkSum[512];    // block sums for 2-level scan
__device__ int g_psrc[NE];       // src node of dst-sorted edge
__device__ int g_peid[NE];       // original edge id of dst-sorted edge
__device__ __half g_W[768 * DIMC];    // [n][k], QKV concat, fp16 RN
__device__ __half g_WE[DIMC * DIMC];  // [n][k], fp16 RN

// ---------------------------------------------------------------------------
// Warp-MMA helpers (portable PTX: ldmatrix + mma.sync + cp.async, sm_80+)
// ---------------------------------------------------------------------------
__device__ __forceinline__ uint32_t smem_u32(const void* p) {
    uint32_t a;
    asm("{ .reg .u64 t; cvta.to.shared.u64 t, %1; cvt.u32.u64 %0, t; }"
        : "=r"(a) : "l"(p));
    return a;
}
__device__ __forceinline__ void ldsm_x4(uint32_t* r, uint32_t addr) {
    asm volatile("ldmatrix.sync.aligned.m8n8.x4.shared.b16 {%0,%1,%2,%3}, [%4];"
                 : "=r"(r[0]), "=r"(r[1]), "=r"(r[2]), "=r"(r[3]) : "r"(addr));
}
__device__ __forceinline__ void mma_f16(float* d, const uint32_t* a, const uint32_t* b) {
    asm volatile(
        "mma.sync.aligned.m16n8k16.row.col.f32.f16.f16.f32 "
        "{%0,%1,%2,%3}, {%4,%5,%6,%7}, {%8,%9}, {%0,%1,%2,%3};"
        : "+f"(d[0]), "+f"(d[1]), "+f"(d[2]), "+f"(d[3])
        : "r"(a[0]), "r"(a[1]), "r"(a[2]), "r"(a[3]), "r"(b[0]), "r"(b[1]));
}
__device__ __forceinline__ void cp_async16(uint32_t saddr, const void* gptr) {
    asm volatile("cp.async.cg.shared.global [%0], [%1], 16;"
                 :: "r"(saddr), "l"(gptr) : "memory");
}
__device__ __forceinline__ void cp_commit() {
    asm volatile("cp.async.commit_group;" ::: "memory");
}
__device__ __forceinline__ void cp_wait0() {
    asm volatile("cp.async.wait_group 0;" ::: "memory");
}

// ---------------------------------------------------------------------------
// Zero small accumulators (BN sums + histogram).
// ---------------------------------------------------------------------------
__global__ void zero_kernel() {
    int i = blockIdx.x * 256 + threadIdx.x;
    if (i < NN) g_cnt[i] = 0;
    if (i < DIMC) { g_cs[i] = 0.0f; g_cs2[i] = 0.0f; }
}

// ---------------------------------------------------------------------------
// edge_index -> int32 src/dst + dst histogram (int64 or int32 payload).
// ---------------------------------------------------------------------------
__global__ void cvt_idx_kernel(const long long* __restrict__ e64) {
    const int* e32 = (const int*)e64;
    bool is64 = true;
    #pragma unroll
    for (int i = 0; i < 64; ++i)
        if ((e64[i] >> 32) != 0) is64 = false;
    long stride = (long)gridDim.x * blockDim.x;
    for (long e = (long)blockIdx.x * blockDim.x + threadIdx.x; e < NE; e += stride) {
        int s, d;
        if (is64) { s = (int)e64[e]; d = (int)e64[NE + e]; }
        else      { s = e32[e];      d = e32[NE + e];      }
        g_src[e] = s;
        g_dst[e] = d;
        atomicAdd(&g_cnt[d], 1);
    }
}

// ---------------------------------------------------------------------------
// 3-kernel exclusive scan of g_cnt -> g_off / g_cur.
// ---------------------------------------------------------------------------
__global__ void scan1_kernel() {
    __shared__ int sh[256];
    int i = blockIdx.x * 256 + threadIdx.x;
    int v = (i < NN) ? g_cnt[i] : 0;
    sh[threadIdx.x] = v;
    __syncthreads();
    for (int d = 1; d < 256; d <<= 1) {
        int t = (threadIdx.x >= d) ? sh[threadIdx.x - d] : 0;
        __syncthreads();
        sh[threadIdx.x] += t;
        __syncthreads();
    }
    if (i < NN) g_off[i] = sh[threadIdx.x] - v;   // exclusive within block
    if (threadIdx.x == 255) g_blkSum[blockIdx.x] = sh[255];
}
__global__ void scan2_kernel() {   // one block, 512 threads
    __shared__ int sh[512];
    int v = (threadIdx.x < NBLK) ? g_blkSum[threadIdx.x] : 0;
    sh[threadIdx.x] = v;
    __syncthreads();
    for (int d = 1; d < 512; d <<= 1) {
        int t = (threadIdx.x >= d) ? sh[threadIdx.x - d] : 0;
        __syncthreads();
        sh[threadIdx.x] += t;
        __syncthreads();
    }
    if (threadIdx.x < NBLK) g_blkSum[threadIdx.x] = sh[threadIdx.x] - v;  // exclusive
}
__global__ void scan3_kernel() {
    int i = blockIdx.x * 256 + threadIdx.x;
    if (i < NN) {
        int o = g_off[i] + g_blkSum[blockIdx.x];
        g_off[i] = o;
        g_cur[i] = o;
    }
    if (i == 0) g_off[NN] = NE;
}

// ---------------------------------------------------------------------------
// Build dst-sorted edge list (CSR payload).
// ---------------------------------------------------------------------------
__global__ void build_kernel() {
    int e = blockIdx.x * 256 + threadIdx.x;
    if (e < NE) {
        int d = g_dst[e];
        int pos = atomicAdd(&g_cur[d], 1);
        g_psrc[pos] = g_src[e];
        g_peid[pos] = e;
    }
}

// ---------------------------------------------------------------------------
// Weights transposed into B-operand layout [n][k], fp16 round-to-nearest.
// ---------------------------------------------------------------------------
__global__ void prep_w_kernel(const float* __restrict__ WQ, const float* __restrict__ WK,
                              const float* __restrict__ WV, const float* __restrict__ WE) {
    int i = blockIdx.x * 256 + threadIdx.x;   // 0 .. 1024*256-1
    if (i < 768 * DIMC) {
        int n = i >> 8;
        int k = i & 255;
        int m = n >> 8, nn = n & 255;
        const float* W = (m == 0) ? WQ : (m == 1) ? WK : WV;
        g_W[i] = __float2half_rn(W[k * DIMC + nn]);
    } else {
        int j = i - 768 * DIMC;
        int n = j >> 8, k = j & 255;
        g_WE[j] = __float2half_rn(WE[k * DIMC + n]);
    }
}

// ---------------------------------------------------------------------------
// Convert & store one A chunk (4 float4 per thread) to fp16 smem stage.
// ---------------------------------------------------------------------------
__device__ __forceinline__ void stsA(char* stage, const float4* v4,
                                     const int* aRow, int aC4) {
    __half* sA = (__half*)stage;
    #pragma unroll
    for (int l = 0; l < 4; ++l) {
        float4 v = v4[l];
        __half2 h01 = __floats2half2_rn(v.x, v.y);
        __half2 h23 = __floats2half2_rn(v.z, v.w);
        int row = aRow[l];
        *(uint2*)(sA + row * 40 + aC4 * 4) =
            make_uint2(*(uint32_t*)&h01, *(uint32_t*)&h23);
    }
}

// ---------------------------------------------------------------------------
// Warp-MMA fp16 GEMM (1-pass), 128x128 block tile, K=256 in 8 chunks of 32.
// (unchanged from round-12 best)
// EDGE=0: writes Q/K/V.  EDGE=1: per-edge head-score epilogue -> g_S.
// ---------------------------------------------------------------------------
template<int EDGE>
__global__ void __launch_bounds__(256, 2) mma_gemm_kernel(const float* __restrict__ Asrc) {
    extern __shared__ __align__(16) char dsm[];
    __shared__ int Ssrc[128], Sdst[128];

    const int tid  = threadIdx.x;
    const int wid  = tid >> 5;
    const int lane = tid & 31;
    const int wm   = wid & 3;
    const int wn   = wid >> 2;
    const int quad = lane & 3;
    const int qrow = lane >> 2;

    const int row0  = blockIdx.y * 128;
    const int nbase = blockIdx.x * 128;
    const int Mtot  = EDGE ? NE : NN;

    if (EDGE && tid < 128) {
        int ge = row0 + tid;
        if (ge > NE - 1) ge = NE - 1;
        Ssrc[tid] = g_src[ge];
        Sdst[tid] = g_dst[ge];
    }

    const float4* A4 = (const float4*)Asrc;
    const uint4* B4 = EDGE ? (const uint4*)g_WE : (const uint4*)g_W;

    float acc[2][8][4] = {};

    const uint32_t base = smem_u32(dsm);
    const uint32_t aOff = (uint32_t)((wm * 32 + (lane & 15)) * 80 + (lane >> 4) * 16);
    const uint32_t bOffX4 = (uint32_t)((wn * 64 + (lane & 7) + (lane >> 4) * 8) * 80 +
                                       ((lane >> 3) & 1) * 16);

    const int aRow[4] = { (tid + 0) >> 3, (tid + 256) >> 3, (tid + 512) >> 3, (tid + 768) >> 3 };
    const int aC4 = tid & 7;
    long aRowG[4];
    #pragma unroll
    for (int l = 0; l < 4; ++l) aRowG[l] = min(row0 + aRow[l], Mtot - 1);
    const int bRow[2] = { (tid + 0) >> 2, (tid + 256) >> 2 };
    const int bC4 = tid & 3;

    float4 aPre[4];
    #pragma unroll
    for (int l = 0; l < 4; ++l) aPre[l] = A4[aRowG[l] * 64 + 0 + aC4];
    {
        uint32_t bB = base + B_BASE;
        #pragma unroll
        for (int l = 0; l < 2; ++l) {
            const uint4* gsrc = B4 + (long)(nbase + bRow[l]) * 32 + 0 + bC4;
            cp_async16(bB + (uint32_t)(bRow[l] * 80 + bC4 * 16), gsrc);
        }
        cp_commit();
    }

    for (int kc = 0; kc < 8; ++kc) {
        const int st = kc & 1;
        const uint32_t aBase = base + st * A_STAGE_BYTES;
        const uint32_t bBase = base + B_BASE + st * B_STAGE_BYTES;

        stsA(dsm + st * A_STAGE_BYTES, aPre, aRow, aC4);

        cp_wait0();
        __syncthreads();

        if (kc < 7) {
            uint32_t bBn = base + B_BASE + (st ^ 1) * B_STAGE_BYTES;
            #pragma unroll
            for (int l = 0; l < 2; ++l) {
                const uint4* gsrc = B4 + (long)(nbase + bRow[l]) * 32 + (kc + 1) * 4 + bC4;
                cp_async16(bBn + (uint32_t)(bRow[l] * 80 + bC4 * 16), gsrc);
            }
            cp_commit();
            #pragma unroll
            for (int l = 0; l < 4; ++l)
                aPre[l] = A4[aRowG[l] * 64 + (kc + 1) * 8 + aC4];
        }

        #pragma unroll
        for (int s = 0; s < 2; ++s) {
            uint32_t ah[2][4];
            #pragma unroll
            for (int mi = 0; mi < 2; ++mi) {
                uint32_t o = aOff + (uint32_t)(mi * 16 * 80 + s * 32);
                ldsm_x4(ah[mi], aBase + o);
            }
            #pragma unroll
            for (int nj = 0; nj < 4; ++nj) {
                const int ni = nj * 2;
                uint32_t bo = bOffX4 + (uint32_t)(nj * 16 * 80 + s * 32);
                uint32_t bf[4];
                ldsm_x4(bf, bBase + bo);
                mma_f16(acc[0][ni],     ah[0], bf + 0);
                mma_f16(acc[0][ni + 1], ah[0], bf + 2);
                mma_f16(acc[1][ni],     ah[1], bf + 0);
                mma_f16(acc[1][ni + 1], ah[1], bf + 2);
            }
        }
    }

    if (EDGE) {
        const float scale = 0.17677669529663687f;  // 1/sqrt(32)
        #pragma unroll
        for (int mi = 0; mi < 2; ++mi) {
            #pragma unroll
            for (int rh = 0; rh < 2; ++rh) {
                int r  = wm * 32 + mi * 16 + qrow + rh * 8;
                int ge = row0 + r;
                const float* Kr = g_K + (long)Ssrc[r] * DIMC + nbase + wn * 64;
                const float* Qr = g_Q + (long)Sdst[r] * DIMC + nbase + wn * 64;
                #pragma unroll
                for (int h = 0; h < 2; ++h) {
                    float p = 0.0f;
                    #pragma unroll
                    for (int j = 0; j < 4; ++j) {
                        int ni = h * 4 + j;
                        int c  = ni * 8 + quad * 2;
                        float2 kv = *(const float2*)(Kr + c);
                        float2 qv = *(const float2*)(Qr + c);
                        p += acc[mi][ni][rh * 2 + 0] * kv.x * qv.x;
                        p += acc[mi][ni][rh * 2 + 1] * kv.y * qv.y;
                    }
                    p += __shfl_xor_sync(0xffffffffu, p, 1);
                    p += __shfl_xor_sync(0xffffffffu, p, 2);
                    if (quad == 0 && ge < NE) {
                        float sv = fminf(5.0f, fmaxf(-5.0f, p * scale));
                        g_S[(long)ge * NH + (nbase >> 5) + wn * 2 + h] = expf(sv);
                    }
                }
            }
        }
    } else {
        int bx = blockIdx.x;
        float* Cout = (bx < 2) ? g_Q : (bx < 4) ? g_K : g_V;
        int colb = (bx & 1) * 128;
        #pragma unroll
        for (int mi = 0; mi < 2; ++mi) {
            #pragma unroll
            for (int ni = 0; ni < 8; ++ni) {
                int r = row0 + wm * 32 + mi * 16 + qrow;
                int c = colb + wn * 64 + ni * 8 + quad * 2;
                if (r < NN)
                    *(float2*)(Cout + (long)r * DIMC + c) =
                        make_float2(acc[mi][ni][0], acc[mi][ni][1]);
                if (r + 8 < NN)
                    *(float2*)(Cout + (long)(r + 8) * DIMC + c) =
                        make_float2(acc[mi][ni][2], acc[mi][ni][3]);
            }
        }
    }
}

// ---------------------------------------------------------------------------
// Gather + residual: one CTA per node; thread = column.
//   out[n][c] = x[n][c] + (sum_{e in edges(n)} V[src_e][c] * s_e[h]) / (Z + eps)
// Register accumulation; no atomics. 2-way unrolled edge loop for load ILP.
// ---------------------------------------------------------------------------
__global__ void gather_resid_kernel(const float* __restrict__ x,
                                    float* __restrict__ out) {
    int n   = blockIdx.x;
    int tid = threadIdx.x;
    int h   = tid >> 5;
    int beg = g_off[n];
    int end = g_off[n + 1];

    float acc = 0.0f, zacc = 0.0f;
    int e = beg;
    for (; e + 1 < end; e += 2) {
        int s0 = g_psrc[e],     s1 = g_psrc[e + 1];
        int i0 = g_peid[e],     i1 = g_peid[e + 1];
        float w0 = g_S[(long)i0 * NH + h];
        float w1 = g_S[(long)i1 * NH + h];
        float v0 = g_V[(long)s0 * DIMC + tid];
        float v1 = g_V[(long)s1 * DIMC + tid];
        acc += v0 * w0;
        acc += v1 * w1;
        zacc += w0 + w1;
    }
    if (e < end) {
        int s0 = g_psrc[e];
        int i0 = g_peid[e];
        float w0 = g_S[(long)i0 * NH + h];
        acc += g_V[(long)s0 * DIMC + tid] * w0;
        zacc += w0;
    }
    out[(long)n * DIMC + tid] = x[(long)n * DIMC + tid] + acc / (zacc + 1e-6f);
}

// ---------------------------------------------------------------------------
// BN column sums over out, then normalize.
// ---------------------------------------------------------------------------
__global__ void stats_kernel(const float* __restrict__ out) {
    int c = threadIdx.x;
    int r0 = blockIdx.x * 256;
    int rend = min(NN, r0 + 256);
    float s = 0.0f, s2 = 0.0f;
    for (int n = r0; n < rend; ++n) {
        float hv = out[(long)n * DIMC + c];
        s += hv;
        s2 += hv * hv;
    }
    atomicAdd(&g_cs[c], s);
    atomicAdd(&g_cs2[c], s2);
}

__global__ void bn_norm_kernel(float* __restrict__ out,
                               const float* __restrict__ gamma,
                               const float* __restrict__ beta) {
    long total = (long)NN * DIMC;
    long stride = (long)gridDim.x * blockDim.x;
    const float invN = 1.0f / (float)NN;
    for (long i = (long)blockIdx.x * blockDim.x + threadIdx.x; i < total; i += stride) {
        int c = (int)(i & (DIMC - 1));
        float mean = g_cs[c] * invN;
        float var = g_cs2[c] * invN - mean * mean;
        out[i] = (out[i] - mean) * rsqrtf(var + 1e-5f) * gamma[c] + beta[c];
    }
}

extern "C" void kernel_launch(void* const* d_in, const int* in_sizes, int n_in,
                              void* d_out, int out_size) {
    const float* x     = (const float*)d_in[0];
    const float* ea    = (const float*)d_in[1];
    const float* WQ    = (const float*)d_in[2];
    const float* WK    = (const float*)d_in[3];
    const float* WE    = (const float*)d_in[4];
    const float* WV    = (const float*)d_in[5];
    const float* gamma = (const float*)d_in[6];
    const float* beta  = (const float*)d_in[7];
    const long long* eidx = (const long long*)d_in[8];
    float* out = (float*)d_out;

    zero_kernel<<<NBLK, 256>>>();
    cvt_idx_kernel<<<512, 256>>>(eidx);
    scan1_kernel<<<NBLK, 256>>>();
    scan2_kernel<<<1, 512>>>();
    scan3_kernel<<<NBLK, 256>>>();
    build_kernel<<<(NE + 255) / 256, 256>>>();
    prep_w_kernel<<<1024, 256>>>(WQ, WK, WV, WE);

    // QKV: x = N-tile (6), y = row-tile (782) -> schedule-adjacent CTAs share A.
    mma_gemm_kernel<0><<<dim3(6, 782), 256, DYN_SMEM>>>(x);
    // Edge: x = N-tile (2), y = row-tile (3907).
    mma_gemm_kernel<1><<<dim3(2, 3907), 256, DYN_SMEM>>>(ea);

    gather_resid_kernel<<<NN, 256>>>(x, out);
    stats_kernel<<<NBLK, 256>>>(out);
    bn_norm_kernel<<<2048, 256>>>(out, gamma, beta);
}

// round 14
// speedup vs baseline: 1.7831x; 1.0523x over previous
#include <cuda_runtime.h>
#include <cuda_fp16.h>
#include <math.h>
#include <stdint.h>

#define NN 100000
#define NE 500000
#define DIMC 256
#define NH 8
#define NBLK 391   // ceil(NN/256)

// Dynamic smem layout (bytes):
//   A stage s (s=0,1): base + s*10240          (single fp16 copy of A chunk)
//   B stage s:         base + 20480 + s*10240  (single fp16 copy of W chunk)
#define A_STAGE_BYTES 10240
#define B_BASE        20480
#define B_STAGE_BYTES 10240
#define DYN_SMEM      40960

// ---------------------------------------------------------------------------
// Device-global scratch (no allocation allowed in kernel_launch)
// ---------------------------------------------------------------------------
__device__ __half g_Qh[NN * DIMC];
__device__ __half g_Kh[NN * DIMC];
__device__ __half g_Vh[NN * DIMC];
__device__ float g_S[NE * NH];
__device__ float g_cs[DIMC];
__device__ float g_cs2[DIMC];
__device__ int g_src[NE];
__device__ int g_dst[NE];
__device__ int g_cnt[NN];        // per-dst degree histogram
__device__ int g_off[NN + 1];    // CSR offsets (exclusive scan of cnt)
__device__ int g_cur[NN];        // running cursor for build pass
__device__ int g_blkSum[512];    // block sums for 2-level scan
__device__ int g_psrc[NE];       // src node of dst-sorted edge
__device__ int g_peid[NE];       // original edge id of dst-sorted edge
__device__ __half g_W[768 * DIMC];    // [n][k], QKV concat, fp16 RN
__device__ __half g_WE[DIMC * DIMC];  // [n][k], fp16 RN

// ---------------------------------------------------------------------------
// Warp-MMA helpers (portable PTX: ldmatrix + mma.sync + cp.async, sm_80+)
// ---------------------------------------------------------------------------
__device__ __forceinline__ uint32_t smem_u32(const void* p) {
    uint32_t a;
    asm("{ .reg .u64 t; cvta.to.shared.u64 t, %1; cvt.u32.u64 %0, t; }"
        : "=r"(a) : "l"(p));
    return a;
}
__device__ __forceinline__ void ldsm_x4(uint32_t* r, uint32_t addr) {
    asm volatile("ldmatrix.sync.aligned.m8n8.x4.shared.b16 {%0,%1,%2,%3}, [%4];"
                 : "=r"(r[0]), "=r"(r[1]), "=r"(r[2]), "=r"(r[3]) : "r"(addr));
}
__device__ __forceinline__ void mma_f16(float* d, const uint32_t* a, const uint32_t* b) {
    asm volatile(
        "mma.sync.aligned.m16n8k16.row.col.f32.f16.f16.f32 "
        "{%0,%1,%2,%3}, {%4,%5,%6,%7}, {%8,%9}, {%0,%1,%2,%3};"
        : "+f"(d[0]), "+f"(d[1]), "+f"(d[2]), "+f"(d[3])
        : "r"(a[0]), "r"(a[1]), "r"(a[2]), "r"(a[3]), "r"(b[0]), "r"(b[1]));
}
__device__ __forceinline__ void cp_async16(uint32_t saddr, const void* gptr) {
    asm volatile("cp.async.cg.shared.global [%0], [%1], 16;"
                 :: "r"(saddr), "l"(gptr) : "memory");
}
__device__ __forceinline__ void cp_commit() {
    asm volatile("cp.async.commit_group;" ::: "memory");
}
__device__ __forceinline__ void cp_wait0() {
    asm volatile("cp.async.wait_group 0;" ::: "memory");
}

// ---------------------------------------------------------------------------
// Zero small accumulators (BN sums + histogram).
// ---------------------------------------------------------------------------
__global__ void zero_kernel() {
    int i = blockIdx.x * 256 + threadIdx.x;
    if (i < NN) g_cnt[i] = 0;
    if (i < DIMC) { g_cs[i] = 0.0f; g_cs2[i] = 0.0f; }
}

// ---------------------------------------------------------------------------
// edge_index -> int32 src/dst + dst histogram (int64 or int32 payload).
// ---------------------------------------------------------------------------
__global__ void cvt_idx_kernel(const long long* __restrict__ e64) {
    const int* e32 = (const int*)e64;
    bool is64 = true;
    #pragma unroll
    for (int i = 0; i < 64; ++i)
        if ((e64[i] >> 32) != 0) is64 = false;
    long stride = (long)gridDim.x * blockDim.x;
    for (long e = (long)blockIdx.x * blockDim.x + threadIdx.x; e < NE; e += stride) {
        int s, d;
        if (is64) { s = (int)e64[e]; d = (int)e64[NE + e]; }
        else      { s = e32[e];      d = e32[NE + e];      }
        g_src[e] = s;
        g_dst[e] = d;
        atomicAdd(&g_cnt[d], 1);
    }
}

// ---------------------------------------------------------------------------
// 3-kernel exclusive scan of g_cnt -> g_off / g_cur.
// ---------------------------------------------------------------------------
__global__ void scan1_kernel() {
    __shared__ int sh[256];
    int i = blockIdx.x * 256 + threadIdx.x;
    int v = (i < NN) ? g_cnt[i] : 0;
    sh[threadIdx.x] = v;
    __syncthreads();
    for (int d = 1; d < 256; d <<= 1) {
        int t = (threadIdx.x >= d) ? sh[threadIdx.x - d] : 0;
        __syncthreads();
        sh[threadIdx.x] += t;
        __syncthreads();
    }
    if (i < NN) g_off[i] = sh[threadIdx.x] - v;   // exclusive within block
    if (threadIdx.x == 255) g_blkSum[blockIdx.x] = sh[255];
}
__global__ void scan2_kernel() {   // one block, 512 threads
    __shared__ int sh[512];
    int v = (threadIdx.x < NBLK) ? g_blkSum[threadIdx.x] : 0;
    sh[threadIdx.x] = v;
    __syncthreads();
    for (int d = 1; d < 512; d <<= 1) {
        int t = (threadIdx.x >= d) ? sh[threadIdx.x - d] : 0;
        __syncthreads();
        sh[threadIdx.x] += t;
        __syncthreads();
    }
    if (threadIdx.x < NBLK) g_blkSum[threadIdx.x] = sh[threadIdx.x] - v;  // exclusive
}
__global__ void scan3_kernel() {
    int i = blockIdx.x * 256 + threadIdx.x;
    if (i < NN) {
        int o = g_off[i] + g_blkSum[blockIdx.x];
        g_off[i] = o;
        g_cur[i] = o;
    }
    if (i == 0) g_off[NN] = NE;
}

// ---------------------------------------------------------------------------
// Build dst-sorted edge list (CSR payload).
// ---------------------------------------------------------------------------
__global__ void build_kernel() {
    int e = blockIdx.x * 256 + threadIdx.x;
    if (e < NE) {
        int d = g_dst[e];
        int pos = atomicAdd(&g_cur[d], 1);
        g_psrc[pos] = g_src[e];
        g_peid[pos] = e;
    }
}

// ---------------------------------------------------------------------------
// Weights transposed into B-operand layout [n][k], fp16 round-to-nearest.
// ---------------------------------------------------------------------------
__global__ void prep_w_kernel(const float* __restrict__ WQ, const float* __restrict__ WK,
                              const float* __restrict__ WV, const float* __restrict__ WE) {
    int i = blockIdx.x * 256 + threadIdx.x;   // 0 .. 1024*256-1
    if (i < 768 * DIMC) {
        int n = i >> 8;
        int k = i & 255;
        int m = n >> 8, nn = n & 255;
        const float* W = (m == 0) ? WQ : (m == 1) ? WK : WV;
        g_W[i] = __float2half_rn(W[k * DIMC + nn]);
    } else {
        int j = i - 768 * DIMC;
        int n = j >> 8, k = j & 255;
        g_WE[j] = __float2half_rn(WE[k * DIMC + n]);
    }
}

// ---------------------------------------------------------------------------
// Convert & store one A chunk (4 float4 per thread) to fp16 smem stage.
// ---------------------------------------------------------------------------
__device__ __forceinline__ void stsA(char* stage, const float4* v4,
                                     const int* aRow, int aC4) {
    __half* sA = (__half*)stage;
    #pragma unroll
    for (int l = 0; l < 4; ++l) {
        float4 v = v4[l];
        __half2 h01 = __floats2half2_rn(v.x, v.y);
        __half2 h23 = __floats2half2_rn(v.z, v.w);
        int row = aRow[l];
        *(uint2*)(sA + row * 40 + aC4 * 4) =
            make_uint2(*(uint32_t*)&h01, *(uint32_t*)&h23);
    }
}

// ---------------------------------------------------------------------------
// Warp-MMA fp16 GEMM (1-pass), 128x128 block tile, K=256 in 8 chunks of 32.
// EDGE=0: writes Q/K/V as fp16.  EDGE=1: per-edge head-score epilogue -> g_S
// (K/Q gathered as fp16, converted in registers).
// ---------------------------------------------------------------------------
template<int EDGE>
__global__ void __launch_bounds__(256, 2) mma_gemm_kernel(const float* __restrict__ Asrc) {
    extern __shared__ __align__(16) char dsm[];
    __shared__ int Ssrc[128], Sdst[128];

    const int tid  = threadIdx.x;
    const int wid  = tid >> 5;
    const int lane = tid & 31;
    const int wm   = wid & 3;
    const int wn   = wid >> 2;
    const int quad = lane & 3;
    const int qrow = lane >> 2;

    const int row0  = blockIdx.y * 128;
    const int nbase = blockIdx.x * 128;
    const int Mtot  = EDGE ? NE : NN;

    if (EDGE && tid < 128) {
        int ge = row0 + tid;
        if (ge > NE - 1) ge = NE - 1;
        Ssrc[tid] = g_src[ge];
        Sdst[tid] = g_dst[ge];
    }

    const float4* A4 = (const float4*)Asrc;
    const uint4* B4 = EDGE ? (const uint4*)g_WE : (const uint4*)g_W;

    float acc[2][8][4] = {};

    const uint32_t base = smem_u32(dsm);
    const uint32_t aOff = (uint32_t)((wm * 32 + (lane & 15)) * 80 + (lane >> 4) * 16);
    const uint32_t bOffX4 = (uint32_t)((wn * 64 + (lane & 7) + (lane >> 4) * 8) * 80 +
                                       ((lane >> 3) & 1) * 16);

    const int aRow[4] = { (tid + 0) >> 3, (tid + 256) >> 3, (tid + 512) >> 3, (tid + 768) >> 3 };
    const int aC4 = tid & 7;
    long aRowG[4];
    #pragma unroll
    for (int l = 0; l < 4; ++l) aRowG[l] = min(row0 + aRow[l], Mtot - 1);
    const int bRow[2] = { (tid + 0) >> 2, (tid + 256) >> 2 };
    const int bC4 = tid & 3;

    float4 aPre[4];
    #pragma unroll
    for (int l = 0; l < 4; ++l) aPre[l] = A4[aRowG[l] * 64 + 0 + aC4];
    {
        uint32_t bB = base + B_BASE;
        #pragma unroll
        for (int l = 0; l < 2; ++l) {
            const uint4* gsrc = B4 + (long)(nbase + bRow[l]) * 32 + 0 + bC4;
            cp_async16(bB + (uint32_t)(bRow[l] * 80 + bC4 * 16), gsrc);
        }
        cp_commit();
    }

    for (int kc = 0; kc < 8; ++kc) {
        const int st = kc & 1;
        const uint32_t aBase = base + st * A_STAGE_BYTES;
        const uint32_t bBase = base + B_BASE + st * B_STAGE_BYTES;

        stsA(dsm + st * A_STAGE_BYTES, aPre, aRow, aC4);

        cp_wait0();
        __syncthreads();

        if (kc < 7) {
            uint32_t bBn = base + B_BASE + (st ^ 1) * B_STAGE_BYTES;
            #pragma unroll
            for (int l = 0; l < 2; ++l) {
                const uint4* gsrc = B4 + (long)(nbase + bRow[l]) * 32 + (kc + 1) * 4 + bC4;
                cp_async16(bBn + (uint32_t)(bRow[l] * 80 + bC4 * 16), gsrc);
            }
            cp_commit();
            #pragma unroll
            for (int l = 0; l < 4; ++l)
                aPre[l] = A4[aRowG[l] * 64 + (kc + 1) * 8 + aC4];
        }

        #pragma unroll
        for (int s = 0; s < 2; ++s) {
            uint32_t ah[2][4];
            #pragma unroll
            for (int mi = 0; mi < 2; ++mi) {
                uint32_t o = aOff + (uint32_t)(mi * 16 * 80 + s * 32);
                ldsm_x4(ah[mi], aBase + o);
            }
            #pragma unroll
            for (int nj = 0; nj < 4; ++nj) {
                const int ni = nj * 2;
                uint32_t bo = bOffX4 + (uint32_t)(nj * 16 * 80 + s * 32);
                uint32_t bf[4];
                ldsm_x4(bf, bBase + bo);
                mma_f16(acc[0][ni],     ah[0], bf + 0);
                mma_f16(acc[0][ni + 1], ah[0], bf + 2);
                mma_f16(acc[1][ni],     ah[1], bf + 0);
                mma_f16(acc[1][ni + 1], ah[1], bf + 2);
            }
        }
    }

    if (EDGE) {
        const float scale = 0.17677669529663687f;  // 1/sqrt(32)
        #pragma unroll
        for (int mi = 0; mi < 2; ++mi) {
            #pragma unroll
            for (int rh = 0; rh < 2; ++rh) {
                int r  = wm * 32 + mi * 16 + qrow + rh * 8;
                int ge = row0 + r;
                const __half* Kr = g_Kh + (long)Ssrc[r] * DIMC + nbase + wn * 64;
                const __half* Qr = g_Qh + (long)Sdst[r] * DIMC + nbase + wn * 64;
                #pragma unroll
                for (int h = 0; h < 2; ++h) {
                    float p = 0.0f;
                    #pragma unroll
                    for (int j = 0; j < 4; ++j) {
                        int ni = h * 4 + j;
                        int c  = ni * 8 + quad * 2;
                        float2 kv = __half22float2(*(const __half2*)(Kr + c));
                        float2 qv = __half22float2(*(const __half2*)(Qr + c));
                        p += acc[mi][ni][rh * 2 + 0] * kv.x * qv.x;
                        p += acc[mi][ni][rh * 2 + 1] * kv.y * qv.y;
                    }
                    p += __shfl_xor_sync(0xffffffffu, p, 1);
                    p += __shfl_xor_sync(0xffffffffu, p, 2);
                    if (quad == 0 && ge < NE) {
                        float sv = fminf(5.0f, fmaxf(-5.0f, p * scale));
                        g_S[(long)ge * NH + (nbase >> 5) + wn * 2 + h] = expf(sv);
                    }
                }
            }
        }
    } else {
        int bx = blockIdx.x;
        __half* Cout = (bx < 2) ? g_Qh : (bx < 4) ? g_Kh : g_Vh;
        int colb = (bx & 1) * 128;
        #pragma unroll
        for (int mi = 0; mi < 2; ++mi) {
            #pragma unroll
            for (int ni = 0; ni < 8; ++ni) {
                int r = row0 + wm * 32 + mi * 16 + qrow;
                int c = colb + wn * 64 + ni * 8 + quad * 2;
                if (r < NN) {
                    __half2 v = __floats2half2_rn(acc[mi][ni][0], acc[mi][ni][1]);
                    *(__half2*)(Cout + (long)r * DIMC + c) = v;
                }
                if (r + 8 < NN) {
                    __half2 v = __floats2half2_rn(acc[mi][ni][2], acc[mi][ni][3]);
                    *(__half2*)(Cout + (long)(r + 8) * DIMC + c) = v;
                }
            }
        }
    }
}

// ---------------------------------------------------------------------------
// Gather + residual: one CTA per node; thread = column.
//   out[n][c] = x[n][c] + (sum_{e in edges(n)} V[src_e][c] * s_e[h]) / (Z + eps)
// Register accumulation; no atomics. V gathered as fp16.
// ---------------------------------------------------------------------------
__global__ void gather_resid_kernel(const float* __restrict__ x,
                                    float* __restrict__ out) {
    int n   = blockIdx.x;
    int tid = threadIdx.x;
    int h   = tid >> 5;
    int beg = g_off[n];
    int end = g_off[n + 1];

    float acc = 0.0f, zacc = 0.0f;
    int e = beg;
    for (; e + 1 < end; e += 2) {
        int s0 = g_psrc[e],     s1 = g_psrc[e + 1];
        int i0 = g_peid[e],     i1 = g_peid[e + 1];
        float w0 = g_S[(long)i0 * NH + h];
        float w1 = g_S[(long)i1 * NH + h];
        float v0 = __half2float(g_Vh[(long)s0 * DIMC + tid]);
        float v1 = __half2float(g_Vh[(long)s1 * DIMC + tid]);
        acc += v0 * w0;
        acc += v1 * w1;
        zacc += w0 + w1;
    }
    if (e < end) {
        int s0 = g_psrc[e];
        int i0 = g_peid[e];
        float w0 = g_S[(long)i0 * NH + h];
        acc += __half2float(g_Vh[(long)s0 * DIMC + tid]) * w0;
        zacc += w0;
    }
    out[(long)n * DIMC + tid] = x[(long)n * DIMC + tid] + acc / (zacc + 1e-6f);
}

// ---------------------------------------------------------------------------
// BN column sums over out, then normalize.
// ---------------------------------------------------------------------------
__global__ void stats_kernel(const float* __restrict__ out) {
    int c = threadIdx.x;
    int r0 = blockIdx.x * 256;
    int rend = min(NN, r0 + 256);
    float s = 0.0f, s2 = 0.0f;
    for (int n = r0; n < rend; ++n) {
        float hv = out[(long)n * DIMC + c];
        s += hv;
        s2 += hv * hv;
    }
    atomicAdd(&g_cs[c], s);
    atomicAdd(&g_cs2[c], s2);
}

__global__ void bn_norm_kernel(float* __restrict__ out,
                               const float* __restrict__ gamma,
                               const float* __restrict__ beta) {
    long total = (long)NN * DIMC;
    long stride = (long)gridDim.x * blockDim.x;
    const float invN = 1.0f / (float)NN;
    for (long i = (long)blockIdx.x * blockDim.x + threadIdx.x; i < total; i += stride) {
        int c = (int)(i & (DIMC - 1));
        float mean = g_cs[c] * invN;
        float var = g_cs2[c] * invN - mean * mean;
        out[i] = (out[i] - mean) * rsqrtf(var + 1e-5f) * gamma[c] + beta[c];
    }
}

extern "C" void kernel_launch(void* const* d_in, const int* in_sizes, int n_in,
                              void* d_out, int out_size) {
    const float* x     = (const float*)d_in[0];
    const float* ea    = (const float*)d_in[1];
    const float* WQ    = (const float*)d_in[2];
    const float* WK    = (const float*)d_in[3];
    const float* WE    = (const float*)d_in[4];
    const float* WV    = (const float*)d_in[5];
    const float* gamma = (const float*)d_in[6];
    const float* beta  = (const float*)d_in[7];
    const long long* eidx = (const long long*)d_in[8];
    float* out = (float*)d_out;

    zero_kernel<<<NBLK, 256>>>();
    cvt_idx_kernel<<<512, 256>>>(eidx);
    scan1_kernel<<<NBLK, 256>>>();
    scan2_kernel<<<1, 512>>>();
    scan3_kernel<<<NBLK, 256>>>();
    build_kernel<<<(NE + 255) / 256, 256>>>();
    prep_w_kernel<<<1024, 256>>>(WQ, WK, WV, WE);

    // QKV: x = N-tile (6), y = row-tile (782) -> schedule-adjacent CTAs share A.
    mma_gemm_kernel<0><<<dim3(6, 782), 256, DYN_SMEM>>>(x);
    // Edge: x = N-tile (2), y = row-tile (3907).
    mma_gemm_kernel<1><<<dim3(2, 3907), 256, DYN_SMEM>>>(ea);

    gather_resid_kernel<<<NN, 256>>>(x, out);
    stats_kernel<<<NBLK, 256>>>(out);
    bn_norm_kernel<<<2048, 256>>>(out, gamma, beta);
}